// round 6
// baseline (speedup 1.0000x reference)
#include <cuda_runtime.h>
#include <cstdint>

#define BB   64
#define LL   128
#define TE   256
#define CIN  256
#define HH   512
#define CAT  768
#define G4   2048
#define OUTN 128
#define NBLK 144
#define NTHR 256

typedef unsigned long long ull;

// ---------------- persistent device buffers ----------------
__device__ float g_pe[(size_t)BB * TE * HH];   // proj_enc (32 MB)
__device__ float g_pdp[8 * 64 * HH];           // pd partials (8 slices)  1 MB
__device__ float g_xp[6 * 64 * CIN];           // xhat partials (x:0-1, ctx:2-5) 384KB
__device__ float g_zp[6 * 64 * G4];            // z partials (h:0-3, x:4-5) 3 MB (also epi O1)
__device__ float g_fp[6 * 64 * 3 * HH];        // cfc partials (h:0-3, x:4-5) 2.25MB (also epi O2)
__device__ float g_h[BB * HH];
__device__ float g_c[BB * HH];
__device__ float g_ctx[BB * HH];
__device__ float g_hlstm[BB * HH];
__device__ float g_hid[BB * HH];
__device__ float g_w6[G4 * CAT];               // [W_ih | W_hh]
__device__ float g_w3[3 * HH * CAT];           // [W_ff1 ; W_ff2 ; W_ta+W_tb]
__device__ float g_b3[3 * HH];
__device__ unsigned g_bcnt;
__device__ unsigned g_bgen;

// ---------------- helpers ----------------
__device__ __forceinline__ float fast_tanh(float x) {
    float y;
    asm("tanh.approx.f32 %0, %1;" : "=f"(y) : "f"(x));
    return y;
}
__device__ __forceinline__ float sigm(float x) {
    return 1.0f / (1.0f + __expf(-x));
}
__device__ __forceinline__ ull pk2(float a, float b) {
    ull r;
    asm("mov.b64 %0, {%1, %2};" : "=l"(r) : "f"(a), "f"(b));
    return r;
}
__device__ __forceinline__ void upk2(ull v, float& a, float& b) {
    asm("mov.b64 {%0, %1}, %2;" : "=f"(a), "=f"(b) : "l"(v));
}
#define FMA2(d, a, b) asm("fma.rn.f32x2 %0, %1, %2, %0;" : "+l"(d) : "l"(a), "l"(b))

// ---------------- global barrier (all NBLK blocks co-resident) ----------------
__device__ __forceinline__ void gsync() {
    __syncthreads();
    if (threadIdx.x == 0) {
        unsigned gen = atomicAdd(&g_bgen, 0u);
        __threadfence();
        if (atomicAdd(&g_bcnt, 1u) == NBLK - 1) {
            g_bcnt = 0;
            __threadfence();
            atomicAdd(&g_bgen, 1u);
        } else {
            while (atomicAdd(&g_bgen, 0u) == gen) { __nanosleep(64); }
        }
        __threadfence();
    }
    __syncthreads();
}

// ---------------- shared memory union ----------------
struct SmemG { float X[32][68]; float W[32][132]; };
struct SmemA { float pds[HH]; float wss[HH]; float se[TE]; float ss[TE]; float red[NTHR]; };
union Smem { SmemG g; SmemA a; };

// ---------------- 64x128 GEMM tile, 256 threads, 8x4 thread tile, f32x2 FMA ----
// Normal mode (xfold==0): X row m: cols [0,K0) from X0+m*str0, cols >= K0 from
// X1 + m*str1 + (k - K0).  Fold mode (xfold>0): X[m][k] = sum_{s<xfold}
// X0[(s*64+m)*CIN + k] + xfb[k] (k in [0,256)).
// klen % 32 == 0; each 32-chunk fully on one side of the concat.
__device__ __noinline__ void gemm_t(const float* __restrict__ X0, int K0, int str0,
                                    const float* __restrict__ X1, int str1,
                                    const float* __restrict__ W, int wstr, int n0,
                                    int kbeg, int klen,
                                    float* __restrict__ dst, int dstr,
                                    const float* __restrict__ bias, SmemG& s,
                                    int xfold, const float* __restrict__ xfb) {
    const int tid = threadIdx.x;
    const int m  = tid >> 2, q = tid & 3;        // X loader
    const int n  = tid >> 3, c = tid & 7;        // W loader
    const int tx = tid & 31, ty = tid >> 5;      // compute
    float xr[8], wreg[16];
    ull acc[8][2];
#pragma unroll
    for (int r = 0; r < 8; r++) { acc[r][0] = 0ull; acc[r][1] = 0ull; }

    auto loadregs = [&](int kg0) {
        int kg = kg0 + q * 8;
        float4 v0, v1;
        if (xfold) {
            v0 = make_float4(0.f, 0.f, 0.f, 0.f);
            v1 = v0;
            for (int sl = 0; sl < xfold; sl++) {
                const float* p = X0 + (size_t)(sl * 64 + m) * CIN + kg;
                float4 a0 = *(const float4*)p;
                float4 a1 = *(const float4*)(p + 4);
                v0.x += a0.x; v0.y += a0.y; v0.z += a0.z; v0.w += a0.w;
                v1.x += a1.x; v1.y += a1.y; v1.z += a1.z; v1.w += a1.w;
            }
            float4 b0 = *(const float4*)(xfb + kg);
            float4 b1 = *(const float4*)(xfb + kg + 4);
            v0.x += b0.x; v0.y += b0.y; v0.z += b0.z; v0.w += b0.w;
            v1.x += b1.x; v1.y += b1.y; v1.z += b1.z; v1.w += b1.w;
        } else {
            const float* xs = (kg < K0) ? (X0 + (size_t)m * str0 + kg)
                                        : (X1 + (size_t)m * str1 + (kg - K0));
            v0 = *(const float4*)xs;
            v1 = *(const float4*)(xs + 4);
        }
        xr[0] = v0.x; xr[1] = v0.y; xr[2] = v0.z; xr[3] = v0.w;
        xr[4] = v1.x; xr[5] = v1.y; xr[6] = v1.z; xr[7] = v1.w;
#pragma unroll
        for (int r = 0; r < 4; r++) {
            const float* wrp = W + (size_t)(n0 + n + 32 * r) * wstr + kg0;
#pragma unroll
            for (int i = 0; i < 4; i++) wreg[r * 4 + i] = wrp[c + 8 * i];
        }
    };

    loadregs(kbeg);
    for (int kb = 0; kb < klen; kb += 32) {
#pragma unroll
        for (int j = 0; j < 8; j++) s.X[q * 8 + j][m] = xr[j];
#pragma unroll
        for (int r = 0; r < 4; r++)
#pragma unroll
            for (int i = 0; i < 4; i++) s.W[c + 8 * i][n + 32 * r] = wreg[r * 4 + i];
        __syncthreads();
        if (kb + 32 < klen) loadregs(kbeg + kb + 32);
#pragma unroll
        for (int k = 0; k < 32; k++) {
            float4 bv = *(const float4*)&s.W[k][tx * 4];
            ull b01 = pk2(bv.x, bv.y);
            ull b23 = pk2(bv.z, bv.w);
            float4 a0 = *(const float4*)&s.X[k][ty * 8];
            float4 a1 = *(const float4*)&s.X[k][ty * 8 + 4];
            const float av[8] = {a0.x, a0.y, a0.z, a0.w, a1.x, a1.y, a1.z, a1.w};
#pragma unroll
            for (int r = 0; r < 8; r++) {
                ull ad = pk2(av[r], av[r]);
                FMA2(acc[r][0], ad, b01);
                FMA2(acc[r][1], ad, b23);
            }
        }
        __syncthreads();
    }
#pragma unroll
    for (int r = 0; r < 8; r++) {
        int mm = ty * 8 + r;
        int nn = n0 + tx * 4;
        float4 v;
        upk2(acc[r][0], v.x, v.y);
        upk2(acc[r][1], v.z, v.w);
        if (bias) {
            v.x += bias[nn]; v.y += bias[nn + 1]; v.z += bias[nn + 2]; v.w += bias[nn + 3];
        }
        *(float4*)(dst + (size_t)mm * dstr + nn) = v;
    }
}

// ---------------- per-batch attention (one block per batch) ----------------
__device__ __noinline__ void attention(int b, const float* __restrict__ h_en,
                                       const float* __restrict__ w_score, SmemA& a) {
    const int tid = threadIdx.x;
    // reduce pd partials (8 slices)
    for (int h = tid; h < HH; h += NTHR) {
        float sacc = 0.0f;
#pragma unroll
        for (int sl = 0; sl < 8; sl++)
            sacc += g_pdp[(size_t)(sl * 64 + b) * HH + h];
        a.pds[h] = sacc;
        a.wss[h] = w_score[h];
    }
    __syncthreads();
    // e scores: 8 warps, 32 t's each
    const int warp = tid >> 5, lane = tid & 31;
    const float4* pds4 = (const float4*)a.pds;
    const float4* wss4 = (const float4*)a.wss;
    for (int tt = 0; tt < 32; tt++) {
        int t = warp + 8 * tt;
        const float4* pe4 = (const float4*)(g_pe + ((size_t)b * TE + t) * HH);
        float acc = 0.0f;
#pragma unroll
        for (int i = 0; i < 4; i++) {
            int h4 = lane + 32 * i;
            float4 p = pe4[h4];
            float4 d = pds4[h4];
            float4 w = wss4[h4];
            acc += w.x * fast_tanh(p.x + d.x);
            acc += w.y * fast_tanh(p.y + d.y);
            acc += w.z * fast_tanh(p.z + d.z);
            acc += w.w * fast_tanh(p.w + d.w);
        }
#pragma unroll
        for (int off = 16; off > 0; off >>= 1)
            acc += __shfl_down_sync(0xffffffffu, acc, off);
        if (lane == 0) a.se[t] = acc;
    }
    __syncthreads();
    // softmax over TE=256
    float ev = a.se[tid];
    a.red[tid] = ev;
    __syncthreads();
    for (int s = 128; s > 0; s >>= 1) {
        if (tid < s) a.red[tid] = fmaxf(a.red[tid], a.red[tid + s]);
        __syncthreads();
    }
    float mx = a.red[0];
    __syncthreads();
    float p = __expf(ev - mx);
    a.red[tid] = p;
    __syncthreads();
    for (int s = 128; s > 0; s >>= 1) {
        if (tid < s) a.red[tid] += a.red[tid + s];
        __syncthreads();
    }
    float inv = 1.0f / a.red[0];
    a.ss[tid] = p * inv;
    __syncthreads();
    // context
    for (int m = tid; m < HH; m += NTHR) {
        const float* hb = h_en + (size_t)b * TE * HH + m;
        float a0 = 0, a1 = 0, a2 = 0, a3 = 0;
        for (int t = 0; t < TE; t += 4) {
            a0 += a.ss[t + 0] * hb[(size_t)(t + 0) * HH];
            a1 += a.ss[t + 1] * hb[(size_t)(t + 1) * HH];
            a2 += a.ss[t + 2] * hb[(size_t)(t + 2) * HH];
            a3 += a.ss[t + 3] * hb[(size_t)(t + 3) * HH];
        }
        g_ctx[b * HH + m] = (a0 + a1) + (a2 + a3);
    }
}

// ---------------- weight packing (separate small kernel) ----------------
__global__ void k_pack(const float* __restrict__ W_ih, const float* __restrict__ W_hh,
                       const float* __restrict__ W_ff1, const float* __restrict__ W_ff2,
                       const float* __restrict__ W_ta, const float* __restrict__ W_tb,
                       const float* __restrict__ b_ff1, const float* __restrict__ b_ff2,
                       const float* __restrict__ b_ta, const float* __restrict__ b_tb) {
    const int N6 = G4 * CAT;
    const int N3 = 3 * HH * CAT;
    const int NB2 = 3 * HH;
    int total = N6 + N3 + NB2;
    for (int i = blockIdx.x * blockDim.x + threadIdx.x; i < total; i += gridDim.x * blockDim.x) {
        if (i < N6) {
            int nn = i / CAT, k = i % CAT;
            g_w6[i] = (k < CIN) ? W_ih[nn * CIN + k] : W_hh[nn * HH + (k - CIN)];
        } else if (i < N6 + N3) {
            int j = i - N6;
            int nn = j / CAT, k = j % CAT;
            int gate = nn / HH, u = nn % HH;
            float v;
            if (gate == 0)      v = W_ff1[u * CAT + k];
            else if (gate == 1) v = W_ff2[u * CAT + k];
            else                v = W_ta[u * CAT + k] + W_tb[u * CAT + k];
            g_w3[j] = v;
        } else {
            int nn = i - N6 - N3;
            int gate = nn / HH, u = nn % HH;
            g_b3[nn] = (gate == 0) ? b_ff1[u] : (gate == 1) ? b_ff2[u] : (b_ta[u] + b_tb[u]);
        }
    }
}

// ---------------- the persistent uber-kernel ----------------
__global__ void __launch_bounds__(NTHR, 1)
k_main(const float* __restrict__ x, const float* __restrict__ h_en,
       const float* __restrict__ W_dec, const float* __restrict__ W_enc,
       const float* __restrict__ b_enc, const float* __restrict__ w_score,
       const float* __restrict__ W_yattn, const float* __restrict__ b_yattn,
       const float* __restrict__ b_ih,
       const float* __restrict__ W_o1, const float* __restrict__ b_o1,
       const float* __restrict__ W_o2, const float* __restrict__ b_o2,
       float* __restrict__ out, int write_state) {
    __shared__ Smem sm;
    const int bid = blockIdx.x;
    const int tid = threadIdx.x;
    const int gstep = NBLK * NTHR;

    // ---- P0: init h,c + proj_enc ----
    for (int idx = bid * NTHR + tid; idx < BB * HH; idx += gstep) {
        g_h[idx] = 0.0f; g_c[idx] = 0.0f;
    }
    for (int j = bid; j < 1024; j += NBLK) {       // 256 m-tiles x 4 n-tiles, full K=512
        int mt = j >> 2, nt = j & 3;
        gemm_t(h_en + (size_t)mt * 64 * HH, HH, HH, h_en, 0,
               W_enc, HH, nt * 128, 0, HH,
               g_pe + (size_t)mt * 64 * HH, HH, b_enc, sm.g, 0, nullptr);
    }
    gsync();

    for (int t = 0; t < LL; t++) {
        const float* xt = x + (size_t)t * CIN;
        // ---- P1: pd split8 (32) + xhat-x split2 (4) + zh slices 0-1 (32) = 68 jobs ----
        for (int j = bid; j < 68; j += NBLK) {
            if (j < 32) {
                int nt = j >> 3, ks = j & 7;
                gemm_t(g_h, HH, HH, g_c, HH,
                       W_dec, 1024, nt * 128, ks * 128, 128,
                       g_pdp + (size_t)ks * 64 * HH, HH, nullptr, sm.g, 0, nullptr);
            } else if (j < 36) {
                int q = j - 32, nt = q >> 1, ks = q & 1;
                gemm_t(xt, CIN, LL * CIN, xt, 0,
                       W_yattn, CAT, nt * 128, ks * 128, 128,
                       g_xp + (size_t)ks * 64 * CIN, CIN, nullptr, sm.g, 0, nullptr);
            } else {
                // z h-part: k in [CIN, CIN+256); K0=CIN so X1 index = k - CIN into h
                int q = j - 36, nt = q >> 1, ks = q & 1;
                gemm_t(g_h, CIN, 0, g_h, HH,
                       g_w6, CAT, nt * 128, CIN + ks * 128, 128,
                       g_zp + (size_t)ks * 64 * G4, G4, nullptr, sm.g, 0, nullptr);
            }
        }
        gsync();
        // ---- P2: attention (blocks 0-63) || zh slices 2-3 (32 jobs, blocks 64+) ----
        if (bid < 64) {
            attention(bid, h_en, w_score, sm.a);
        } else {
            for (int j = bid - 64; j < 32; j += NBLK - 64) {
                int nt = j >> 1, ks = (j & 1) + 2;
                gemm_t(g_h, CIN, 0, g_h, HH,
                       g_w6, CAT, nt * 128, CIN + ks * 128, 128,
                       g_zp + (size_t)ks * 64 * G4, G4, nullptr, sm.g, 0, nullptr);
            }
        }
        gsync();
        // ---- P3: xhat ctx-part split4 (8 jobs -> xp slices 2-5) ----
        for (int j = bid; j < 8; j += NBLK) {
            int nt = j >> 2, ks = j & 3;
            gemm_t(xt, CIN, LL * CIN, g_ctx, HH,
                   W_yattn, CAT, nt * 128, CIN + ks * 128, 128,
                   g_xp + (size_t)(2 + ks) * 64 * CIN, CIN, nullptr, sm.g, 0, nullptr);
        }
        gsync();
        // ---- P4: zx (32 jobs, zp slices 4-5) + cfcx (24 jobs, fp slices 4-5), X = folded xhat ----
        for (int j = bid; j < 56; j += NBLK) {
            if (j < 32) {
                int nt = j >> 1, ks = j & 1;
                gemm_t(g_xp, 0, 0, nullptr, 0,
                       g_w6, CAT, nt * 128, ks * 128, 128,
                       g_zp + (size_t)(4 + ks) * 64 * G4, G4, nullptr, sm.g, 6, b_yattn);
            } else {
                int q = j - 32, nt = q >> 1, ks = q & 1;
                gemm_t(g_xp, 0, 0, nullptr, 0,
                       g_w3, CAT, nt * 128, ks * 128, 128,
                       g_fp + (size_t)(4 + ks) * 64 * (3 * HH), 3 * HH, nullptr, sm.g, 6, b_yattn);
            }
        }
        gsync();
        // ---- P5: LSTM pointwise (fold zp slices 0-5) ----
        for (int idx = bid * NTHR + tid; idx < BB * HH; idx += gstep) {
            int m = idx >> 9, u = idx & 511;
            float zi = b_ih[u], zg = b_ih[u + 512], zf = b_ih[u + 1024], zo = b_ih[u + 1536];
#pragma unroll
            for (int sl = 0; sl < 6; sl++) {
                const float* p = g_zp + (size_t)(sl * 64 + m) * G4;
                zi += p[u]; zg += p[u + 512]; zf += p[u + 1024]; zo += p[u + 1536];
            }
            float c_old = g_c[idx];
            float nc = c_old * sigm(zf + 1.0f) + tanhf(zi) * sigm(zg);
            g_c[idx] = nc;
            g_hlstm[idx] = tanhf(nc) * sigm(zo);
        }
        gsync();
        // ---- P6: cfc h-part (48 jobs, fp slices 0-3), k in [CIN, CIN+512) ----
        for (int j = bid; j < 48; j += NBLK) {
            int nt = j >> 2, ks = j & 3;
            gemm_t(g_hlstm, CIN, 0, g_hlstm, HH,
                   g_w3, CAT, nt * 128, CIN + ks * 128, 128,
                   g_fp + (size_t)ks * 64 * (3 * HH), 3 * HH, nullptr, sm.g, 0, nullptr);
        }
        gsync();
        // ---- P7: CfC pointwise (fold fp slices 0-5) -> new h ----
        for (int idx = bid * NTHR + tid; idx < BB * HH; idx += gstep) {
            int m = idx >> 9, u = idx & 511;
            float f1 = g_b3[u], f2 = g_b3[u + 512], tg = g_b3[u + 1024];
#pragma unroll
            for (int sl = 0; sl < 6; sl++) {
                const float* p = g_fp + (size_t)(sl * 64 + m) * (3 * HH);
                f1 += p[u]; f2 += p[u + 512]; tg += p[u + 1024];
            }
            float ti = sigm(tg);
            g_h[idx] = tanhf(f1) * (1.0f - ti) + ti * tanhf(f2);
        }
        gsync();
    }

    // ---- E1: O1 GEMM ([h|ctx], K=1024): 4nt x 8 slices klen128 -> zp (stride HH) ----
    for (int j = bid; j < 32; j += NBLK) {
        int nt = j >> 3, ks = j & 7;
        gemm_t(g_h, HH, HH, g_ctx, HH,
               W_o1, 1024, nt * 128, ks * 128, 128,
               g_zp + (size_t)ks * 64 * HH, HH, nullptr, sm.g, 0, nullptr);
    }
    gsync();
    // ---- E2: reduce 8 + leaky relu -> g_hid ----
    for (int idx = bid * NTHR + tid; idx < BB * HH; idx += gstep) {
        int m = idx >> 9, u = idx & 511;
        float s = b_o1[u];
#pragma unroll
        for (int sl = 0; sl < 8; sl++)
            s += g_zp[(size_t)(sl * 64 + m) * HH + u];
        g_hid[idx] = (s > 0.0f) ? s : 0.01f * s;
    }
    gsync();
    // ---- E3: O2 GEMM (hid, K=512): 4 slices klen128 -> fp (stride OUTN) ----
    for (int j = bid; j < 4; j += NBLK) {
        int ks = j;
        gemm_t(g_hid, HH, HH, g_hid, 0,
               W_o2, HH, 0, ks * 128, 128,
               g_fp + (size_t)ks * 64 * OUTN, OUTN, nullptr, sm.g, 0, nullptr);
    }
    gsync();
    // ---- E4: final reduce + bias (+ optional state copy) ----
    for (int idx = bid * NTHR + tid; idx < BB * OUTN; idx += gstep) {
        int m = idx >> 7, u = idx & 127;
        float s = b_o2[u];
#pragma unroll
        for (int sl = 0; sl < 4; sl++)
            s += g_fp[(size_t)(sl * 64 + m) * OUTN + u];
        out[idx] = s;
    }
    if (write_state) {
        for (int idx = bid * NTHR + tid; idx < BB * HH; idx += gstep) {
            out[BB * OUTN + idx] = g_h[idx];
            out[BB * OUTN + BB * HH + idx] = g_c[idx];
        }
    }
}

// ============================================================================
extern "C" void kernel_launch(void* const* d_in, const int* in_sizes, int n_in,
                              void* d_out, int out_size) {
    const float* x       = (const float*)d_in[0];
    const float* h_en    = (const float*)d_in[1];
    const float* W_dec   = (const float*)d_in[2];
    const float* W_enc   = (const float*)d_in[3];
    const float* b_enc   = (const float*)d_in[4];
    const float* w_score = (const float*)d_in[5];
    const float* W_yattn = (const float*)d_in[6];
    const float* b_yattn = (const float*)d_in[7];
    const float* W_ih    = (const float*)d_in[8];
    const float* b_ih    = (const float*)d_in[9];
    const float* W_hh    = (const float*)d_in[10];
    const float* W_ff1   = (const float*)d_in[11];
    const float* b_ff1   = (const float*)d_in[12];
    const float* W_ff2   = (const float*)d_in[13];
    const float* b_ff2   = (const float*)d_in[14];
    const float* W_ta    = (const float*)d_in[15];
    const float* b_ta    = (const float*)d_in[16];
    const float* W_tb    = (const float*)d_in[17];
    const float* b_tb    = (const float*)d_in[18];
    const float* W_o1    = (const float*)d_in[19];
    const float* b_o1    = (const float*)d_in[20];
    const float* W_o2    = (const float*)d_in[21];
    const float* b_o2    = (const float*)d_in[22];
    float* out = (float*)d_out;

    int write_state = (out_size >= BB * OUTN + 2 * BB * HH) ? 1 : 0;

    k_pack<<<512, 256>>>(W_ih, W_hh, W_ff1, W_ff2, W_ta, W_tb,
                         b_ff1, b_ff2, b_ta, b_tb);
    k_main<<<NBLK, NTHR>>>(x, h_en, W_dec, W_enc, b_enc, w_score,
                           W_yattn, b_yattn, b_ih, W_o1, b_o1, W_o2, b_o2,
                           out, write_state);
}

// round 8
// speedup vs baseline: 1.1731x; 1.1731x over previous
#include <cuda_runtime.h>
#include <cstdint>

#define BB   64
#define LL   128
#define TE   256
#define CIN  256
#define HH   512
#define CAT  768
#define G4   2048
#define OUTN 128
#define NBLK 288
#define NTHR 256

// ---------------- persistent device buffers ----------------
__device__ float g_pe[(size_t)BB * TE * HH];   // proj_enc (32 MB)
__device__ float g_pdp[16 * 64 * HH];          // pd partials (16 slices) 2 MB
__device__ float g_xp[12 * 64 * CIN];          // xhat partials (xx:0-3, xc:4-11)
__device__ float g_zp[12 * 64 * G4];           // z partials (zh:0-7, zx:8-11) 6 MB (epi O1 scratch)
__device__ float g_fp[12 * 64 * 3 * HH];       // cfc partials (h:0-7, x:8-11) 4.5 MB (epi O2 scratch)
__device__ float g_h[BB * HH];
__device__ float g_c[BB * HH];
__device__ float g_ctx[BB * HH];
__device__ float g_xhat[BB * CIN];
__device__ float g_hlstm[BB * HH];
__device__ float g_hid[BB * HH];
__device__ float g_w6[G4 * CAT];               // [W_ih | W_hh]
__device__ float g_w3[3 * HH * CAT];           // [W_ff1 ; W_ff2 ; W_ta+W_tb]
__device__ float g_b3[3 * HH];
__device__ unsigned g_bcnt;
__device__ unsigned g_bgen;

// ---------------- helpers ----------------
__device__ __forceinline__ float fast_tanh(float x) {
    float y;
    asm("tanh.approx.f32 %0, %1;" : "=f"(y) : "f"(x));
    return y;
}
__device__ __forceinline__ float sigm(float x) {
    return 1.0f / (1.0f + __expf(-x));
}

// ---------------- global barrier (all NBLK blocks co-resident) ----------------
__device__ __forceinline__ void gsync() {
    __syncthreads();
    if (threadIdx.x == 0) {
        unsigned gen = atomicAdd(&g_bgen, 0u);
        __threadfence();
        if (atomicAdd(&g_bcnt, 1u) == NBLK - 1) {
            g_bcnt = 0;
            __threadfence();
            atomicAdd(&g_bgen, 1u);
        } else {
            while (atomicAdd(&g_bgen, 0u) == gen) { __nanosleep(32); }
        }
        __threadfence();
    }
    __syncthreads();
}

// ---------------- shared memory union ----------------
// Pad = 68 floats (272 B, multiple of 16) so vector LDS stay aligned.
struct SmemG { float X[64][68]; float W[64][68]; };
struct SmemA { float pds[HH]; float wss[HH]; float se[TE]; float ss[TE]; float red[NTHR]; };
union Smem { SmemG g; SmemA a; };

// ---------------- 64x64 GEMM tile, 256 threads, 4x4 thread tile, plain FFMA ----
// X row m: cols [0,K0) from X0 + m*str0, cols >= K0 from X1 + m*str1 + (k-K0).
// W row-major (wstr). klen % 64 == 0, kbeg % 64 == 0; K0 % 64 == 0 so each
// 64-chunk lies entirely on one side of the concat.
__device__ __noinline__ void gemm64(const float* __restrict__ X0, int K0, int str0,
                                    const float* __restrict__ X1, int str1,
                                    const float* __restrict__ W, int wstr, int n0,
                                    int kbeg, int klen,
                                    float* __restrict__ dst, int dstr,
                                    const float* __restrict__ bias, SmemG& s) {
    const int tid = threadIdx.x;
    const int lr = tid >> 2;      // 0..63  (m-row for X, n-row for W)
    const int q  = tid & 3;       // k-quarter (16 k's each)
    const int tx = tid & 15;      // n-group (4 cols)
    const int ty = tid >> 4;      // m-group (4 rows)
    float acc[4][4] = {};

    for (int kc = kbeg; kc < kbeg + klen; kc += 64) {
        int k0 = kc + q * 16;
        const float* xs = (k0 < K0) ? X0 + (size_t)lr * str0 + k0
                                    : X1 + (size_t)lr * str1 + (k0 - K0);
        const float* wp = W + (size_t)(n0 + lr) * wstr + k0;
#pragma unroll
        for (int j = 0; j < 4; j++) {
            float4 v = *(const float4*)(xs + j * 4);
            int kk = q * 16 + j * 4;
            s.X[kk + 0][lr] = v.x; s.X[kk + 1][lr] = v.y;
            s.X[kk + 2][lr] = v.z; s.X[kk + 3][lr] = v.w;
        }
#pragma unroll
        for (int j = 0; j < 4; j++) {
            float4 v = *(const float4*)(wp + j * 4);
            int kk = q * 16 + j * 4;
            s.W[kk + 0][lr] = v.x; s.W[kk + 1][lr] = v.y;
            s.W[kk + 2][lr] = v.z; s.W[kk + 3][lr] = v.w;
        }
        __syncthreads();
#pragma unroll 16
        for (int k = 0; k < 64; k++) {
            float2 a0 = *(const float2*)&s.X[k][ty * 4];
            float2 a1 = *(const float2*)&s.X[k][ty * 4 + 2];
            float2 b0 = *(const float2*)&s.W[k][tx * 4];
            float2 b1 = *(const float2*)&s.W[k][tx * 4 + 2];
            acc[0][0] += a0.x * b0.x; acc[0][1] += a0.x * b0.y;
            acc[0][2] += a0.x * b1.x; acc[0][3] += a0.x * b1.y;
            acc[1][0] += a0.y * b0.x; acc[1][1] += a0.y * b0.y;
            acc[1][2] += a0.y * b1.x; acc[1][3] += a0.y * b1.y;
            acc[2][0] += a1.x * b0.x; acc[2][1] += a1.x * b0.y;
            acc[2][2] += a1.x * b1.x; acc[2][3] += a1.x * b1.y;
            acc[3][0] += a1.y * b0.x; acc[3][1] += a1.y * b0.y;
            acc[3][2] += a1.y * b1.x; acc[3][3] += a1.y * b1.y;
        }
        __syncthreads();
    }
#pragma unroll
    for (int r = 0; r < 4; r++) {
        int mm = ty * 4 + r;
        int nn = n0 + tx * 4;
        float4 v = make_float4(acc[r][0], acc[r][1], acc[r][2], acc[r][3]);
        if (bias) {
            v.x += bias[nn]; v.y += bias[nn + 1]; v.z += bias[nn + 2]; v.w += bias[nn + 3];
        }
        *(float4*)(dst + (size_t)mm * dstr + nn) = v;
    }
}

// ---------------- per-batch attention (one block per batch) ----------------
__device__ __noinline__ void attention(int b, const float* __restrict__ h_en,
                                       const float* __restrict__ w_score, SmemA& a) {
    const int tid = threadIdx.x;
    // reduce pd partials (16 slices)
    for (int h = tid; h < HH; h += NTHR) {
        float sacc = 0.0f;
#pragma unroll
        for (int sl = 0; sl < 16; sl++)
            sacc += g_pdp[(size_t)(sl * 64 + b) * HH + h];
        a.pds[h] = sacc;
        a.wss[h] = w_score[h];
    }
    __syncthreads();
    // e scores: 8 warps, 32 t's each
    const int warp = tid >> 5, lane = tid & 31;
    const float4* pds4 = (const float4*)a.pds;
    const float4* wss4 = (const float4*)a.wss;
    for (int tt = 0; tt < 32; tt++) {
        int t = warp + 8 * tt;
        const float4* pe4 = (const float4*)(g_pe + ((size_t)b * TE + t) * HH);
        float acc = 0.0f;
#pragma unroll
        for (int i = 0; i < 4; i++) {
            int h4 = lane + 32 * i;
            float4 p = pe4[h4];
            float4 d = pds4[h4];
            float4 w = wss4[h4];
            acc += w.x * fast_tanh(p.x + d.x);
            acc += w.y * fast_tanh(p.y + d.y);
            acc += w.z * fast_tanh(p.z + d.z);
            acc += w.w * fast_tanh(p.w + d.w);
        }
#pragma unroll
        for (int off = 16; off > 0; off >>= 1)
            acc += __shfl_down_sync(0xffffffffu, acc, off);
        if (lane == 0) a.se[t] = acc;
    }
    __syncthreads();
    // softmax over TE=256
    float ev = a.se[tid];
    a.red[tid] = ev;
    __syncthreads();
    for (int s = 128; s > 0; s >>= 1) {
        if (tid < s) a.red[tid] = fmaxf(a.red[tid], a.red[tid + s]);
        __syncthreads();
    }
    float mx = a.red[0];
    __syncthreads();
    float p = __expf(ev - mx);
    a.red[tid] = p;
    __syncthreads();
    for (int s = 128; s > 0; s >>= 1) {
        if (tid < s) a.red[tid] += a.red[tid + s];
        __syncthreads();
    }
    float inv = 1.0f / a.red[0];
    a.ss[tid] = p * inv;
    __syncthreads();
    // context
    for (int m = tid; m < HH; m += NTHR) {
        const float* hb = h_en + (size_t)b * TE * HH + m;
        float a0 = 0, a1 = 0, a2 = 0, a3 = 0;
        for (int t = 0; t < TE; t += 4) {
            a0 += a.ss[t + 0] * hb[(size_t)(t + 0) * HH];
            a1 += a.ss[t + 1] * hb[(size_t)(t + 1) * HH];
            a2 += a.ss[t + 2] * hb[(size_t)(t + 2) * HH];
            a3 += a.ss[t + 3] * hb[(size_t)(t + 3) * HH];
        }
        g_ctx[b * HH + m] = (a0 + a1) + (a2 + a3);
    }
}

// ---------------- weight packing (separate small kernel) ----------------
__global__ void k_pack(const float* __restrict__ W_ih, const float* __restrict__ W_hh,
                       const float* __restrict__ W_ff1, const float* __restrict__ W_ff2,
                       const float* __restrict__ W_ta, const float* __restrict__ W_tb,
                       const float* __restrict__ b_ff1, const float* __restrict__ b_ff2,
                       const float* __restrict__ b_ta, const float* __restrict__ b_tb) {
    const int N6 = G4 * CAT;
    const int N3 = 3 * HH * CAT;
    const int NB2 = 3 * HH;
    int total = N6 + N3 + NB2;
    for (int i = blockIdx.x * blockDim.x + threadIdx.x; i < total; i += gridDim.x * blockDim.x) {
        if (i < N6) {
            int nn = i / CAT, k = i % CAT;
            g_w6[i] = (k < CIN) ? W_ih[nn * CIN + k] : W_hh[nn * HH + (k - CIN)];
        } else if (i < N6 + N3) {
            int j = i - N6;
            int nn = j / CAT, k = j % CAT;
            int gate = nn / HH, u = nn % HH;
            float v;
            if (gate == 0)      v = W_ff1[u * CAT + k];
            else if (gate == 1) v = W_ff2[u * CAT + k];
            else                v = W_ta[u * CAT + k] + W_tb[u * CAT + k];
            g_w3[j] = v;
        } else {
            int nn = i - N6 - N3;
            int gate = nn / HH, u = nn % HH;
            g_b3[nn] = (gate == 0) ? b_ff1[u] : (gate == 1) ? b_ff2[u] : (b_ta[u] + b_tb[u]);
        }
    }
}

// ---------------- the persistent uber-kernel ----------------
__global__ void __launch_bounds__(NTHR, 2)
k_main(const float* __restrict__ x, const float* __restrict__ h_en,
       const float* __restrict__ W_dec, const float* __restrict__ W_enc,
       const float* __restrict__ b_enc, const float* __restrict__ w_score,
       const float* __restrict__ W_yattn, const float* __restrict__ b_yattn,
       const float* __restrict__ b_ih,
       const float* __restrict__ W_o1, const float* __restrict__ b_o1,
       const float* __restrict__ W_o2, const float* __restrict__ b_o2,
       float* __restrict__ out, int write_state) {
    __shared__ Smem sm;
    const int bid = blockIdx.x;
    const int tid = threadIdx.x;
    const int gstep = NBLK * NTHR;

    // ---- P0: init h,c + proj_enc (16384x512 @ W_enc^T + b) ----
    for (int idx = bid * NTHR + tid; idx < BB * HH; idx += gstep) {
        g_h[idx] = 0.0f; g_c[idx] = 0.0f;
    }
    for (int j = bid; j < 2048; j += NBLK) {       // 256 m-tiles x 8 n-tiles, full K=512
        int mt = j >> 3, nt = j & 7;
        gemm64(h_en + (size_t)mt * 64 * HH, HH, HH, h_en, 0,
               W_enc, HH, nt * 64, 0, HH,
               g_pe + (size_t)mt * 64 * HH, HH, b_enc, sm.g);
    }
    gsync();

    for (int t = 0; t < LL; t++) {
        const float* xt = x + (size_t)t * CIN;
        // ---- A: pd (8nt x 16ks = 128) + zh nt 0..19 (20x8 = 160) = 288 jobs ----
        for (int j = bid; j < 288; j += NBLK) {
            if (j < 128) {
                int nt = j >> 4, ks = j & 15;
                gemm64(g_h, HH, HH, g_c, HH,
                       W_dec, 1024, nt * 64, ks * 64, 64,
                       g_pdp + (size_t)ks * 64 * HH, HH, nullptr, sm.g);
            } else {
                int q = j - 128;
                int nt = q >> 3, ks = q & 7;           // nt 0..19
                gemm64(g_h, CIN, 0, g_h, HH,
                       g_w6, CAT, nt * 64, CIN + ks * 64, 64,
                       g_zp + (size_t)ks * 64 * G4, G4, nullptr, sm.g);
            }
        }
        gsync();
        // ---- B: attention (blocks 0-63) || zh nt 20..31 (96) + xx (16) ----
        if (bid < 64) {
            attention(bid, h_en, w_score, sm.a);
        } else {
            for (int j = bid - 64; j < 112; j += NBLK - 64) {
                if (j < 96) {
                    int nt = 20 + (j >> 3), ks = j & 7;
                    gemm64(g_h, CIN, 0, g_h, HH,
                           g_w6, CAT, nt * 64, CIN + ks * 64, 64,
                           g_zp + (size_t)ks * 64 * G4, G4, nullptr, sm.g);
                } else {
                    int q = j - 96;
                    int nt = q >> 2, ks = q & 3;
                    gemm64(xt, CIN, LL * CIN, xt, 0,
                           W_yattn, CAT, nt * 64, ks * 64, 64,
                           g_xp + (size_t)ks * 64 * CIN, CIN, nullptr, sm.g);
                }
            }
        }
        gsync();
        // ---- C: xc (4nt x 8ks = 32 jobs -> xp slices 4..11) ----
        for (int j = bid; j < 32; j += NBLK) {
            int nt = j >> 3, ks = j & 7;
            gemm64(xt, CIN, LL * CIN, g_ctx, HH,
                   W_yattn, CAT, nt * 64, CIN + ks * 64, 64,
                   g_xp + (size_t)(4 + ks) * 64 * CIN, CIN, nullptr, sm.g);
        }
        gsync();
        // ---- C2: reduce xhat (12 slices) + bias -> g_xhat ----
        for (int idx = bid * NTHR + tid; idx < BB * CIN; idx += gstep) {
            int m = idx >> 8, nn = idx & 255;
            float s = b_yattn[nn];
#pragma unroll
            for (int sl = 0; sl < 12; sl++)
                s += g_xp[(size_t)(sl * 64 + m) * CIN + nn];
            g_xhat[idx] = s;
        }
        gsync();
        // ---- D: zx (32nt x 4ks = 128, zp 8-11) + cfcx (24nt x 4ks = 96, fp 8-11) ----
        for (int j = bid; j < 224; j += NBLK) {
            if (j < 128) {
                int nt = j >> 2, ks = j & 3;
                gemm64(g_xhat, CIN, CIN, g_xhat, 0,
                       g_w6, CAT, nt * 64, ks * 64, 64,
                       g_zp + (size_t)(8 + ks) * 64 * G4, G4, nullptr, sm.g);
            } else {
                int q = j - 128;
                int nt = q >> 2, ks = q & 3;
                gemm64(g_xhat, CIN, CIN, g_xhat, 0,
                       g_w3, CAT, nt * 64, ks * 64, 64,
                       g_fp + (size_t)(8 + ks) * 64 * (3 * HH), 3 * HH, nullptr, sm.g);
            }
        }
        gsync();
        // ---- E: LSTM pointwise (fold zp slices 0-11) ----
        for (int idx = bid * NTHR + tid; idx < BB * HH; idx += gstep) {
            int m = idx >> 9, u = idx & 511;
            float zi = b_ih[u], zg = b_ih[u + 512], zf = b_ih[u + 1024], zo = b_ih[u + 1536];
#pragma unroll
            for (int sl = 0; sl < 12; sl++) {
                const float* p = g_zp + (size_t)(sl * 64 + m) * G4;
                zi += p[u]; zg += p[u + 512]; zf += p[u + 1024]; zo += p[u + 1536];
            }
            float c_old = g_c[idx];
            float nc = c_old * sigm(zf + 1.0f) + tanhf(zi) * sigm(zg);
            g_c[idx] = nc;
            g_hlstm[idx] = tanhf(nc) * sigm(zo);
        }
        gsync();
        // ---- F: cfc h-part (24nt x 8ks = 192, fp slices 0-7) ----
        for (int j = bid; j < 192; j += NBLK) {
            int nt = j >> 3, ks = j & 7;
            gemm64(g_hlstm, CIN, 0, g_hlstm, HH,
                   g_w3, CAT, nt * 64, CIN + ks * 64, 64,
                   g_fp + (size_t)ks * 64 * (3 * HH), 3 * HH, nullptr, sm.g);
        }
        gsync();
        // ---- G: CfC pointwise (fold fp slices 0-11) -> new h ----
        for (int idx = bid * NTHR + tid; idx < BB * HH; idx += gstep) {
            int m = idx >> 9, u = idx & 511;
            float f1 = g_b3[u], f2 = g_b3[u + 512], tg = g_b3[u + 1024];
#pragma unroll
            for (int sl = 0; sl < 12; sl++) {
                const float* p = g_fp + (size_t)(sl * 64 + m) * (3 * HH);
                f1 += p[u]; f2 += p[u + 512]; tg += p[u + 1024];
            }
            float ti = sigm(tg);
            g_h[idx] = tanhf(f1) * (1.0f - ti) + ti * tanhf(f2);
        }
        gsync();
    }

    // ---- E1: O1 GEMM ([h|ctx], K=1024): 8nt x 16ks = 128 jobs -> zp (stride HH) ----
    for (int j = bid; j < 128; j += NBLK) {
        int nt = j >> 4, ks = j & 15;
        gemm64(g_h, HH, HH, g_ctx, HH,
               W_o1, 1024, nt * 64, ks * 64, 64,
               g_zp + (size_t)ks * 64 * HH, HH, nullptr, sm.g);
    }
    gsync();
    // ---- E2: reduce 16 + leaky relu -> g_hid ----
    for (int idx = bid * NTHR + tid; idx < BB * HH; idx += gstep) {
        int m = idx >> 9, u = idx & 511;
        float s = b_o1[u];
#pragma unroll
        for (int sl = 0; sl < 16; sl++)
            s += g_zp[(size_t)(sl * 64 + m) * HH + u];
        g_hid[idx] = (s > 0.0f) ? s : 0.01f * s;
    }
    gsync();
    // ---- E3: O2 GEMM (hid, K=512): 2nt x 8ks = 16 jobs -> fp (stride OUTN) ----
    for (int j = bid; j < 16; j += NBLK) {
        int nt = j >> 3, ks = j & 7;
        gemm64(g_hid, HH, HH, g_hid, 0,
               W_o2, HH, nt * 64, ks * 64, 64,
               g_fp + (size_t)ks * 64 * OUTN, OUTN, nullptr, sm.g);
    }
    gsync();
    // ---- E4: final reduce + bias (+ optional state copy) ----
    for (int idx = bid * NTHR + tid; idx < BB * OUTN; idx += gstep) {
        int m = idx >> 7, u = idx & 127;
        float s = b_o2[u];
#pragma unroll
        for (int sl = 0; sl < 8; sl++)
            s += g_fp[(size_t)(sl * 64 + m) * OUTN + u];
        out[idx] = s;
    }
    if (write_state) {
        for (int idx = bid * NTHR + tid; idx < BB * HH; idx += gstep) {
            out[BB * OUTN + idx] = g_h[idx];
            out[BB * OUTN + BB * HH + idx] = g_c[idx];
        }
    }
}

// ============================================================================
extern "C" void kernel_launch(void* const* d_in, const int* in_sizes, int n_in,
                              void* d_out, int out_size) {
    const float* x       = (const float*)d_in[0];
    const float* h_en    = (const float*)d_in[1];
    const float* W_dec   = (const float*)d_in[2];
    const float* W_enc   = (const float*)d_in[3];
    const float* b_enc   = (const float*)d_in[4];
    const float* w_score = (const float*)d_in[5];
    const float* W_yattn = (const float*)d_in[6];
    const float* b_yattn = (const float*)d_in[7];
    const float* W_ih    = (const float*)d_in[8];
    const float* b_ih    = (const float*)d_in[9];
    const float* W_hh    = (const float*)d_in[10];
    const float* W_ff1   = (const float*)d_in[11];
    const float* b_ff1   = (const float*)d_in[12];
    const float* W_ff2   = (const float*)d_in[13];
    const float* b_ff2   = (const float*)d_in[14];
    const float* W_ta    = (const float*)d_in[15];
    const float* b_ta    = (const float*)d_in[16];
    const float* W_tb    = (const float*)d_in[17];
    const float* b_tb    = (const float*)d_in[18];
    const float* W_o1    = (const float*)d_in[19];
    const float* b_o1    = (const float*)d_in[20];
    const float* W_o2    = (const float*)d_in[21];
    const float* b_o2    = (const float*)d_in[22];
    float* out = (float*)d_out;

    int write_state = (out_size >= BB * OUTN + 2 * BB * HH) ? 1 : 0;

    k_pack<<<512, 256>>>(W_ih, W_hh, W_ff1, W_ff2, W_ta, W_tb,
                         b_ff1, b_ff2, b_ta, b_tb);
    k_main<<<NBLK, NTHR>>>(x, h_en, W_dec, W_enc, b_enc, w_score,
                           W_yattn, b_yattn, b_ih, W_o1, b_o1, W_o2, b_o2,
                           out, write_state);
}

// round 9
// speedup vs baseline: 1.2509x; 1.0664x over previous
#include <cuda_runtime.h>
#include <cstdint>

#define BB   64
#define LL   128
#define TE   256
#define CIN  256
#define HH   512
#define CAT  768
#define G4   2048
#define OUTN 128
#define NBLK 288
#define NTHR 256

// ---------------- persistent device buffers ----------------
__device__ float g_pe[(size_t)BB * TE * HH];   // proj_enc (32 MB)
__device__ float g_pdp[16 * 64 * HH];          // pd partials (16 slices) 2 MB
__device__ float g_xp[12 * 64 * CIN];          // xhat partials (xx:0-3, xc:4-11)
__device__ float g_zp[12 * 64 * G4];           // z partials (zh:0-7, zx:8-11) 6 MB (epi O1 scratch)
__device__ float g_fp[12 * 64 * 3 * HH];       // cfc partials (h:0-7, x:8-11) 4.5 MB (epi O2 scratch)
__device__ float g_h[BB * HH];
__device__ float g_c[BB * HH];
__device__ float g_ctx[BB * HH];
__device__ float g_xhat[BB * CIN];
__device__ float g_hlstm[BB * HH];
__device__ float g_hid[BB * HH];
__device__ float g_w6[G4 * CAT];               // [W_ih | W_hh]
__device__ float g_w3[3 * HH * CAT];           // [W_ff1 ; W_ff2 ; W_ta+W_tb]
__device__ float g_b3[3 * HH];
__device__ unsigned long long g_arr;           // monotonic barrier counter

// ---------------- helpers ----------------
__device__ __forceinline__ float fast_tanh(float x) {
    float y;
    asm("tanh.approx.f32 %0, %1;" : "=f"(y) : "f"(x));
    return y;
}
__device__ __forceinline__ float sigm(float x) {
    return 1.0f / (1.0f + __expf(-x));
}

// ---------------- fast global barrier (monotonic counter) ----------------
// Arrival: one atomicAdd per block. Wait: volatile-read spin (no RMW, no sleep).
// bar_t is a per-block local target threaded through the caller.
#define GSYNC() do {                                                     \
    __syncthreads();                                                     \
    if (threadIdx.x == 0) {                                              \
        __threadfence();                                                 \
        bar_t += NBLK;                                                   \
        atomicAdd(&g_arr, 1ull);                                         \
        while (*(volatile unsigned long long*)&g_arr < bar_t) { }        \
        __threadfence();                                                 \
    }                                                                    \
    __syncthreads();                                                     \
} while (0)

// ---------------- shared memory union ----------------
// Pad = 68 floats (272 B, multiple of 16) so vector LDS stay aligned.
struct SmemG { float X[64][68]; float W[64][68]; };
struct SmemA { float pds[HH]; float wss[HH]; float se[TE]; float ss[TE]; float red[NTHR]; };
union Smem { SmemG g; SmemA a; };

// ---------------- 64x64 GEMM tile, 256 threads, 4x4 thread tile, plain FFMA ----
// X row m: cols [0,K0) from X0 + m*str0, cols >= K0 from X1 + m*str1 + (k-K0).
// W row-major (wstr). klen % 64 == 0, kbeg % 64 == 0; K0 % 64 == 0 so each
// 64-chunk lies entirely on one side of the concat.
__device__ __noinline__ void gemm64(const float* __restrict__ X0, int K0, int str0,
                                    const float* __restrict__ X1, int str1,
                                    const float* __restrict__ W, int wstr, int n0,
                                    int kbeg, int klen,
                                    float* __restrict__ dst, int dstr,
                                    const float* __restrict__ bias, SmemG& s) {
    const int tid = threadIdx.x;
    const int lr = tid >> 2;      // 0..63  (m-row for X, n-row for W)
    const int q  = tid & 3;       // k-quarter (16 k's each)
    const int tx = tid & 15;      // n-group (4 cols)
    const int ty = tid >> 4;      // m-group (4 rows)
    float acc[4][4] = {};

    for (int kc = kbeg; kc < kbeg + klen; kc += 64) {
        int k0 = kc + q * 16;
        const float* xs = (k0 < K0) ? X0 + (size_t)lr * str0 + k0
                                    : X1 + (size_t)lr * str1 + (k0 - K0);
        const float* wp = W + (size_t)(n0 + lr) * wstr + k0;
#pragma unroll
        for (int j = 0; j < 4; j++) {
            float4 v = *(const float4*)(xs + j * 4);
            int kk = q * 16 + j * 4;
            s.X[kk + 0][lr] = v.x; s.X[kk + 1][lr] = v.y;
            s.X[kk + 2][lr] = v.z; s.X[kk + 3][lr] = v.w;
        }
#pragma unroll
        for (int j = 0; j < 4; j++) {
            float4 v = *(const float4*)(wp + j * 4);
            int kk = q * 16 + j * 4;
            s.W[kk + 0][lr] = v.x; s.W[kk + 1][lr] = v.y;
            s.W[kk + 2][lr] = v.z; s.W[kk + 3][lr] = v.w;
        }
        __syncthreads();
#pragma unroll 16
        for (int k = 0; k < 64; k++) {
            float2 a0 = *(const float2*)&s.X[k][ty * 4];
            float2 a1 = *(const float2*)&s.X[k][ty * 4 + 2];
            float2 b0 = *(const float2*)&s.W[k][tx * 4];
            float2 b1 = *(const float2*)&s.W[k][tx * 4 + 2];
            acc[0][0] += a0.x * b0.x; acc[0][1] += a0.x * b0.y;
            acc[0][2] += a0.x * b1.x; acc[0][3] += a0.x * b1.y;
            acc[1][0] += a0.y * b0.x; acc[1][1] += a0.y * b0.y;
            acc[1][2] += a0.y * b1.x; acc[1][3] += a0.y * b1.y;
            acc[2][0] += a1.x * b0.x; acc[2][1] += a1.x * b0.y;
            acc[2][2] += a1.x * b1.x; acc[2][3] += a1.x * b1.y;
            acc[3][0] += a1.y * b0.x; acc[3][1] += a1.y * b0.y;
            acc[3][2] += a1.y * b1.x; acc[3][3] += a1.y * b1.y;
        }
        __syncthreads();
    }
#pragma unroll
    for (int r = 0; r < 4; r++) {
        int mm = ty * 4 + r;
        int nn = n0 + tx * 4;
        float4 v = make_float4(acc[r][0], acc[r][1], acc[r][2], acc[r][3]);
        if (bias) {
            v.x += bias[nn]; v.y += bias[nn + 1]; v.z += bias[nn + 2]; v.w += bias[nn + 3];
        }
        *(float4*)(dst + (size_t)mm * dstr + nn) = v;
    }
}

// ---------------- per-batch attention (one block per batch) ----------------
__device__ __noinline__ void attention(int b, const float* __restrict__ h_en,
                                       const float* __restrict__ w_score, SmemA& a) {
    const int tid = threadIdx.x;
    // reduce pd partials (16 slices)
    for (int h = tid; h < HH; h += NTHR) {
        float sacc = 0.0f;
#pragma unroll
        for (int sl = 0; sl < 16; sl++)
            sacc += g_pdp[(size_t)(sl * 64 + b) * HH + h];
        a.pds[h] = sacc;
        a.wss[h] = w_score[h];
    }
    __syncthreads();
    // e scores: 8 warps, 32 t's each
    const int warp = tid >> 5, lane = tid & 31;
    const float4* pds4 = (const float4*)a.pds;
    const float4* wss4 = (const float4*)a.wss;
    for (int tt = 0; tt < 32; tt++) {
        int t = warp + 8 * tt;
        const float4* pe4 = (const float4*)(g_pe + ((size_t)b * TE + t) * HH);
        float acc = 0.0f;
#pragma unroll
        for (int i = 0; i < 4; i++) {
            int h4 = lane + 32 * i;
            float4 p = pe4[h4];
            float4 d = pds4[h4];
            float4 w = wss4[h4];
            acc += w.x * fast_tanh(p.x + d.x);
            acc += w.y * fast_tanh(p.y + d.y);
            acc += w.z * fast_tanh(p.z + d.z);
            acc += w.w * fast_tanh(p.w + d.w);
        }
#pragma unroll
        for (int off = 16; off > 0; off >>= 1)
            acc += __shfl_down_sync(0xffffffffu, acc, off);
        if (lane == 0) a.se[t] = acc;
    }
    __syncthreads();
    // softmax over TE=256
    float ev = a.se[tid];
    a.red[tid] = ev;
    __syncthreads();
    for (int s = 128; s > 0; s >>= 1) {
        if (tid < s) a.red[tid] = fmaxf(a.red[tid], a.red[tid + s]);
        __syncthreads();
    }
    float mx = a.red[0];
    __syncthreads();
    float p = __expf(ev - mx);
    a.red[tid] = p;
    __syncthreads();
    for (int s = 128; s > 0; s >>= 1) {
        if (tid < s) a.red[tid] += a.red[tid + s];
        __syncthreads();
    }
    float inv = 1.0f / a.red[0];
    a.ss[tid] = p * inv;
    __syncthreads();
    // context
    for (int m = tid; m < HH; m += NTHR) {
        const float* hb = h_en + (size_t)b * TE * HH + m;
        float a0 = 0, a1 = 0, a2 = 0, a3 = 0;
        for (int t = 0; t < TE; t += 4) {
            a0 += a.ss[t + 0] * hb[(size_t)(t + 0) * HH];
            a1 += a.ss[t + 1] * hb[(size_t)(t + 1) * HH];
            a2 += a.ss[t + 2] * hb[(size_t)(t + 2) * HH];
            a3 += a.ss[t + 3] * hb[(size_t)(t + 3) * HH];
        }
        g_ctx[b * HH + m] = (a0 + a1) + (a2 + a3);
    }
}

// ---------------- weight packing (separate small kernel) ----------------
__global__ void k_pack(const float* __restrict__ W_ih, const float* __restrict__ W_hh,
                       const float* __restrict__ W_ff1, const float* __restrict__ W_ff2,
                       const float* __restrict__ W_ta, const float* __restrict__ W_tb,
                       const float* __restrict__ b_ff1, const float* __restrict__ b_ff2,
                       const float* __restrict__ b_ta, const float* __restrict__ b_tb) {
    const int N6 = G4 * CAT;
    const int N3 = 3 * HH * CAT;
    const int NB2 = 3 * HH;
    int total = N6 + N3 + NB2;
    for (int i = blockIdx.x * blockDim.x + threadIdx.x; i < total; i += gridDim.x * blockDim.x) {
        if (i < N6) {
            int nn = i / CAT, k = i % CAT;
            g_w6[i] = (k < CIN) ? W_ih[nn * CIN + k] : W_hh[nn * HH + (k - CIN)];
        } else if (i < N6 + N3) {
            int j = i - N6;
            int nn = j / CAT, k = j % CAT;
            int gate = nn / HH, u = nn % HH;
            float v;
            if (gate == 0)      v = W_ff1[u * CAT + k];
            else if (gate == 1) v = W_ff2[u * CAT + k];
            else                v = W_ta[u * CAT + k] + W_tb[u * CAT + k];
            g_w3[j] = v;
        } else {
            int nn = i - N6 - N3;
            int gate = nn / HH, u = nn % HH;
            g_b3[nn] = (gate == 0) ? b_ff1[u] : (gate == 1) ? b_ff2[u] : (b_ta[u] + b_tb[u]);
        }
    }
}

// ---------------- the persistent uber-kernel ----------------
__global__ void __launch_bounds__(NTHR, 2)
k_main(const float* __restrict__ x, const float* __restrict__ h_en,
       const float* __restrict__ W_dec, const float* __restrict__ W_enc,
       const float* __restrict__ b_enc, const float* __restrict__ w_score,
       const float* __restrict__ W_yattn, const float* __restrict__ b_yattn,
       const float* __restrict__ b_ih,
       const float* __restrict__ W_o1, const float* __restrict__ b_o1,
       const float* __restrict__ W_o2, const float* __restrict__ b_o2,
       float* __restrict__ out, int write_state) {
    __shared__ Smem sm;
    const int bid = blockIdx.x;
    const int tid = threadIdx.x;
    const int gstep = NBLK * NTHR;
    unsigned long long bar_t = 0;   // local barrier target

    // ---- P0: init h,c + proj_enc (16384x512 @ W_enc^T + b) ----
    for (int idx = bid * NTHR + tid; idx < BB * HH; idx += gstep) {
        g_h[idx] = 0.0f; g_c[idx] = 0.0f;
    }
    for (int j = bid; j < 2048; j += NBLK) {       // 256 m-tiles x 8 n-tiles, full K=512
        int mt = j >> 3, nt = j & 7;
        gemm64(h_en + (size_t)mt * 64 * HH, HH, HH, h_en, 0,
               W_enc, HH, nt * 64, 0, HH,
               g_pe + (size_t)mt * 64 * HH, HH, b_enc, sm.g);
    }
    GSYNC();

    for (int t = 0; t < LL; t++) {
        const float* xt = x + (size_t)t * CIN;
        // ---- A: pd (8nt x 16ks = 128) + zh nt 0..19 (20x8 = 160) = 288 jobs ----
        for (int j = bid; j < 288; j += NBLK) {
            if (j < 128) {
                int nt = j >> 4, ks = j & 15;
                gemm64(g_h, HH, HH, g_c, HH,
                       W_dec, 1024, nt * 64, ks * 64, 64,
                       g_pdp + (size_t)ks * 64 * HH, HH, nullptr, sm.g);
            } else {
                int q = j - 128;
                int nt = q >> 3, ks = q & 7;           // nt 0..19
                gemm64(g_h, CIN, 0, g_h, HH,
                       g_w6, CAT, nt * 64, CIN + ks * 64, 64,
                       g_zp + (size_t)ks * 64 * G4, G4, nullptr, sm.g);
            }
        }
        GSYNC();
        // ---- B: attention (blocks 0-63) || zh nt 20..31 (96) + xx (16) ----
        if (bid < 64) {
            attention(bid, h_en, w_score, sm.a);
        } else {
            for (int j = bid - 64; j < 112; j += NBLK - 64) {
                if (j < 96) {
                    int nt = 20 + (j >> 3), ks = j & 7;
                    gemm64(g_h, CIN, 0, g_h, HH,
                           g_w6, CAT, nt * 64, CIN + ks * 64, 64,
                           g_zp + (size_t)ks * 64 * G4, G4, nullptr, sm.g);
                } else {
                    int q = j - 96;
                    int nt = q >> 2, ks = q & 3;
                    gemm64(xt, CIN, LL * CIN, xt, 0,
                           W_yattn, CAT, nt * 64, ks * 64, 64,
                           g_xp + (size_t)ks * 64 * CIN, CIN, nullptr, sm.g);
                }
            }
        }
        GSYNC();
        // ---- C: xc (4nt x 8ks = 32 jobs -> xp slices 4..11) ----
        for (int j = bid; j < 32; j += NBLK) {
            int nt = j >> 3, ks = j & 7;
            gemm64(xt, CIN, LL * CIN, g_ctx, HH,
                   W_yattn, CAT, nt * 64, CIN + ks * 64, 64,
                   g_xp + (size_t)(4 + ks) * 64 * CIN, CIN, nullptr, sm.g);
        }
        GSYNC();
        // ---- C2: reduce xhat (12 slices) + bias -> g_xhat ----
        for (int idx = bid * NTHR + tid; idx < BB * CIN; idx += gstep) {
            int m = idx >> 8, nn = idx & 255;
            float s = b_yattn[nn];
#pragma unroll
            for (int sl = 0; sl < 12; sl++)
                s += g_xp[(size_t)(sl * 64 + m) * CIN + nn];
            g_xhat[idx] = s;
        }
        GSYNC();
        // ---- D: zx (32nt x 4ks = 128, zp 8-11) + cfcx (24nt x 4ks = 96, fp 8-11) ----
        for (int j = bid; j < 224; j += NBLK) {
            if (j < 128) {
                int nt = j >> 2, ks = j & 3;
                gemm64(g_xhat, CIN, CIN, g_xhat, 0,
                       g_w6, CAT, nt * 64, ks * 64, 64,
                       g_zp + (size_t)(8 + ks) * 64 * G4, G4, nullptr, sm.g);
            } else {
                int q = j - 128;
                int nt = q >> 2, ks = q & 3;
                gemm64(g_xhat, CIN, CIN, g_xhat, 0,
                       g_w3, CAT, nt * 64, ks * 64, 64,
                       g_fp + (size_t)(8 + ks) * 64 * (3 * HH), 3 * HH, nullptr, sm.g);
            }
        }
        GSYNC();
        // ---- E: LSTM pointwise (fold zp slices 0-11) ----
        for (int idx = bid * NTHR + tid; idx < BB * HH; idx += gstep) {
            int m = idx >> 9, u = idx & 511;
            float zi = b_ih[u], zg = b_ih[u + 512], zf = b_ih[u + 1024], zo = b_ih[u + 1536];
#pragma unroll
            for (int sl = 0; sl < 12; sl++) {
                const float* p = g_zp + (size_t)(sl * 64 + m) * G4;
                zi += p[u]; zg += p[u + 512]; zf += p[u + 1024]; zo += p[u + 1536];
            }
            float c_old = g_c[idx];
            float nc = c_old * sigm(zf + 1.0f) + tanhf(zi) * sigm(zg);
            g_c[idx] = nc;
            g_hlstm[idx] = tanhf(nc) * sigm(zo);
        }
        GSYNC();
        // ---- F: cfc h-part (24nt x 8ks = 192, fp slices 0-7) ----
        for (int j = bid; j < 192; j += NBLK) {
            int nt = j >> 3, ks = j & 7;
            gemm64(g_hlstm, CIN, 0, g_hlstm, HH,
                   g_w3, CAT, nt * 64, CIN + ks * 64, 64,
                   g_fp + (size_t)ks * 64 * (3 * HH), 3 * HH, nullptr, sm.g);
        }
        GSYNC();
        // ---- G: CfC pointwise (fold fp slices 0-11) -> new h ----
        for (int idx = bid * NTHR + tid; idx < BB * HH; idx += gstep) {
            int m = idx >> 9, u = idx & 511;
            float f1 = g_b3[u], f2 = g_b3[u + 512], tg = g_b3[u + 1024];
#pragma unroll
            for (int sl = 0; sl < 12; sl++) {
                const float* p = g_fp + (size_t)(sl * 64 + m) * (3 * HH);
                f1 += p[u]; f2 += p[u + 512]; tg += p[u + 1024];
            }
            float ti = sigm(tg);
            g_h[idx] = tanhf(f1) * (1.0f - ti) + ti * tanhf(f2);
        }
        GSYNC();
    }

    // ---- E1: O1 GEMM ([h|ctx], K=1024): 8nt x 16ks = 128 jobs -> zp (stride HH) ----
    for (int j = bid; j < 128; j += NBLK) {
        int nt = j >> 4, ks = j & 15;
        gemm64(g_h, HH, HH, g_ctx, HH,
               W_o1, 1024, nt * 64, ks * 64, 64,
               g_zp + (size_t)ks * 64 * HH, HH, nullptr, sm.g);
    }
    GSYNC();
    // ---- E2: reduce 16 + leaky relu -> g_hid ----
    for (int idx = bid * NTHR + tid; idx < BB * HH; idx += gstep) {
        int m = idx >> 9, u = idx & 511;
        float s = b_o1[u];
#pragma unroll
        for (int sl = 0; sl < 16; sl++)
            s += g_zp[(size_t)(sl * 64 + m) * HH + u];
        g_hid[idx] = (s > 0.0f) ? s : 0.01f * s;
    }
    GSYNC();
    // ---- E3: O2 GEMM (hid, K=512): 2nt x 8ks = 16 jobs -> fp (stride OUTN) ----
    for (int j = bid; j < 16; j += NBLK) {
        int nt = j >> 3, ks = j & 7;
        gemm64(g_hid, HH, HH, g_hid, 0,
               W_o2, HH, nt * 64, ks * 64, 64,
               g_fp + (size_t)ks * 64 * OUTN, OUTN, nullptr, sm.g);
    }
    GSYNC();
    // ---- last barrier done: bid 0 resets the monotonic counter for the next
    // graph replay (no further GSYNC below, so this is race-free) ----
    if (bid == 0 && tid == 0) {
        atomicExch(&g_arr, 0ull);
    }
    // ---- E4: final reduce + bias (+ optional state copy) ----
    for (int idx = bid * NTHR + tid; idx < BB * OUTN; idx += gstep) {
        int m = idx >> 7, u = idx & 127;
        float s = b_o2[u];
#pragma unroll
        for (int sl = 0; sl < 8; sl++)
            s += g_fp[(size_t)(sl * 64 + m) * OUTN + u];
        out[idx] = s;
    }
    if (write_state) {
        for (int idx = bid * NTHR + tid; idx < BB * HH; idx += gstep) {
            out[BB * OUTN + idx] = g_h[idx];
            out[BB * OUTN + BB * HH + idx] = g_c[idx];
        }
    }
}

// ============================================================================
extern "C" void kernel_launch(void* const* d_in, const int* in_sizes, int n_in,
                              void* d_out, int out_size) {
    const float* x       = (const float*)d_in[0];
    const float* h_en    = (const float*)d_in[1];
    const float* W_dec   = (const float*)d_in[2];
    const float* W_enc   = (const float*)d_in[3];
    const float* b_enc   = (const float*)d_in[4];
    const float* w_score = (const float*)d_in[5];
    const float* W_yattn = (const float*)d_in[6];
    const float* b_yattn = (const float*)d_in[7];
    const float* W_ih    = (const float*)d_in[8];
    const float* b_ih    = (const float*)d_in[9];
    const float* W_hh    = (const float*)d_in[10];
    const float* W_ff1   = (const float*)d_in[11];
    const float* b_ff1   = (const float*)d_in[12];
    const float* W_ff2   = (const float*)d_in[13];
    const float* b_ff2   = (const float*)d_in[14];
    const float* W_ta    = (const float*)d_in[15];
    const float* b_ta    = (const float*)d_in[16];
    const float* W_tb    = (const float*)d_in[17];
    const float* b_tb    = (const float*)d_in[18];
    const float* W_o1    = (const float*)d_in[19];
    const float* b_o1    = (const float*)d_in[20];
    const float* W_o2    = (const float*)d_in[21];
    const float* b_o2    = (const float*)d_in[22];
    float* out = (float*)d_out;

    int write_state = (out_size >= BB * OUTN + 2 * BB * HH) ? 1 : 0;

    k_pack<<<512, 256>>>(W_ih, W_hh, W_ff1, W_ff2, W_ta, W_tb,
                         b_ff1, b_ff2, b_ta, b_tb);
    k_main<<<NBLK, NTHR>>>(x, h_en, W_dec, W_enc, b_enc, w_score,
                           W_yattn, b_yattn, b_ih, W_o1, b_o1, W_o2, b_o2,
                           out, write_state);
}

// round 10
// speedup vs baseline: 1.5200x; 1.2151x over previous
#include <cuda_runtime.h>
#include <cuda_fp16.h>
#include <cstdint>

#define BB   64
#define LL   128
#define TE   256
#define CIN  256
#define HH   512
#define CAT  768
#define G4   2048
#define OUTN 128
#define NBLK 288
#define NTHR 256

// ---------------- persistent device buffers ----------------
__device__ __half g_peh[(size_t)BB * TE * HH]; // proj_enc fp16 (16 MB)
__device__ float g_e[BB * TE];                 // attention scores
__device__ float g_pdp[16 * 64 * HH];          // pd partials (16 slices) 2 MB
__device__ float g_xp[12 * 64 * CIN];          // xhat partials (xx:0-3, xc:4-11)
__device__ float g_zp[12 * 64 * G4];           // z partials (zh:0-7, zx:8-11) 6 MB (epi O1 scratch)
__device__ float g_fp[12 * 64 * 3 * HH];       // cfc partials (h:0-7, x:8-11) 4.5 MB (epi O2 scratch)
__device__ float g_h[BB * HH];
__device__ float g_c[BB * HH];
__device__ float g_ctx[BB * HH];
__device__ float g_xhat[BB * CIN];
__device__ float g_hlstm[BB * HH];
__device__ float g_hid[BB * HH];
__device__ float g_w6[G4 * CAT];               // [W_ih | W_hh]
__device__ float g_w3[3 * HH * CAT];           // [W_ff1 ; W_ff2 ; W_ta+W_tb]
__device__ float g_b3[3 * HH];
__device__ unsigned long long g_arr;           // monotonic barrier counter

// ---------------- helpers ----------------
__device__ __forceinline__ float fast_tanh(float x) {
    float y;
    asm("tanh.approx.f32 %0, %1;" : "=f"(y) : "f"(x));
    return y;
}
__device__ __forceinline__ float sigm(float x) {
    return 1.0f / (1.0f + __expf(-x));
}

// ---------------- fast global barrier (monotonic counter) ----------------
#define GSYNC() do {                                                     \
    __syncthreads();                                                     \
    if (threadIdx.x == 0) {                                              \
        __threadfence();                                                 \
        bar_t += NBLK;                                                   \
        atomicAdd(&g_arr, 1ull);                                         \
        while (*(volatile unsigned long long*)&g_arr < bar_t) { }        \
        __threadfence();                                                 \
    }                                                                    \
    __syncthreads();                                                     \
} while (0)

// ---------------- shared memory union ----------------
struct SmemG { float X[64][68]; float W[64][68]; };
struct SmemA { float pds[HH]; float wss[HH]; float ss[TE]; float red[NTHR]; };
union Smem { SmemG g; SmemA a; };

// ---------------- 64x64 GEMM tile, 256 threads, 4x4 thread tile ----------------
// X row m: cols [0,K0) from X0 + m*str0, cols >= K0 from X1 + m*str1 + (k-K0).
// If dsth != nullptr, output is written as fp16 to dsth instead of fp32 dst.
__device__ __noinline__ void gemm64(const float* __restrict__ X0, int K0, int str0,
                                    const float* __restrict__ X1, int str1,
                                    const float* __restrict__ W, int wstr, int n0,
                                    int kbeg, int klen,
                                    float* __restrict__ dst, int dstr,
                                    const float* __restrict__ bias, SmemG& s,
                                    __half* __restrict__ dsth) {
    const int tid = threadIdx.x;
    const int lr = tid >> 2;      // 0..63  (m-row for X, n-row for W)
    const int q  = tid & 3;       // k-quarter (16 k's each)
    const int tx = tid & 15;      // n-group (4 cols)
    const int ty = tid >> 4;      // m-group (4 rows)
    float acc[4][4] = {};

    for (int kc = kbeg; kc < kbeg + klen; kc += 64) {
        int k0 = kc + q * 16;
        const float* xs = (k0 < K0) ? X0 + (size_t)lr * str0 + k0
                                    : X1 + (size_t)lr * str1 + (k0 - K0);
        const float* wp = W + (size_t)(n0 + lr) * wstr + k0;
#pragma unroll
        for (int j = 0; j < 4; j++) {
            float4 v = *(const float4*)(xs + j * 4);
            int kk = q * 16 + j * 4;
            s.X[kk + 0][lr] = v.x; s.X[kk + 1][lr] = v.y;
            s.X[kk + 2][lr] = v.z; s.X[kk + 3][lr] = v.w;
        }
#pragma unroll
        for (int j = 0; j < 4; j++) {
            float4 v = *(const float4*)(wp + j * 4);
            int kk = q * 16 + j * 4;
            s.W[kk + 0][lr] = v.x; s.W[kk + 1][lr] = v.y;
            s.W[kk + 2][lr] = v.z; s.W[kk + 3][lr] = v.w;
        }
        __syncthreads();
#pragma unroll 16
        for (int k = 0; k < 64; k++) {
            float2 a0 = *(const float2*)&s.X[k][ty * 4];
            float2 a1 = *(const float2*)&s.X[k][ty * 4 + 2];
            float2 b0 = *(const float2*)&s.W[k][tx * 4];
            float2 b1 = *(const float2*)&s.W[k][tx * 4 + 2];
            acc[0][0] += a0.x * b0.x; acc[0][1] += a0.x * b0.y;
            acc[0][2] += a0.x * b1.x; acc[0][3] += a0.x * b1.y;
            acc[1][0] += a0.y * b0.x; acc[1][1] += a0.y * b0.y;
            acc[1][2] += a0.y * b1.x; acc[1][3] += a0.y * b1.y;
            acc[2][0] += a1.x * b0.x; acc[2][1] += a1.x * b0.y;
            acc[2][2] += a1.x * b1.x; acc[2][3] += a1.x * b1.y;
            acc[3][0] += a1.y * b0.x; acc[3][1] += a1.y * b0.y;
            acc[3][2] += a1.y * b1.x; acc[3][3] += a1.y * b1.y;
        }
        __syncthreads();
    }
#pragma unroll
    for (int r = 0; r < 4; r++) {
        int mm = ty * 4 + r;
        int nn = n0 + tx * 4;
        float4 v = make_float4(acc[r][0], acc[r][1], acc[r][2], acc[r][3]);
        if (bias) {
            v.x += bias[nn]; v.y += bias[nn + 1]; v.z += bias[nn + 2]; v.w += bias[nn + 3];
        }
        if (dsth) {
            __half2* p = (__half2*)(dsth + (size_t)mm * dstr + nn);
            p[0] = __floats2half2_rn(v.x, v.y);
            p[1] = __floats2half2_rn(v.z, v.w);
        } else {
            *(float4*)(dst + (size_t)mm * dstr + nn) = v;
        }
    }
}

// ---------------- B1: e-scores for (batch b, t-chunk tc of 32) ----------------
__device__ __noinline__ void escore(int b, int tc, const float* __restrict__ w_score,
                                    SmemA& a) {
    const int tid = threadIdx.x;
    __syncthreads();   // protect smem from previous job's readers
    // cooperative pd reduce (16 slices) into smem + stage w_score
    for (int h = tid; h < HH; h += NTHR) {
        float sacc = 0.0f;
#pragma unroll
        for (int sl = 0; sl < 16; sl++)
            sacc += g_pdp[(size_t)(sl * 64 + b) * HH + h];
        a.pds[h] = sacc;
        a.wss[h] = w_score[h];
    }
    __syncthreads();
    const int warp = tid >> 5, lane = tid & 31;
    // per-lane register copies of pds/wss (16 values each, fixed across t)
    float pd16[16], ws16[16];
    {
        const float4* ps = (const float4*)a.pds;
        const float4* wsv = (const float4*)a.wss;
#pragma unroll
        for (int jj = 0; jj < 2; jj++) {
            int base = (lane + 32 * jj) * 2;
            float4 p0 = ps[base], p1 = ps[base + 1];
            float4 w0 = wsv[base], w1 = wsv[base + 1];
            pd16[jj * 8 + 0] = p0.x; pd16[jj * 8 + 1] = p0.y;
            pd16[jj * 8 + 2] = p0.z; pd16[jj * 8 + 3] = p0.w;
            pd16[jj * 8 + 4] = p1.x; pd16[jj * 8 + 5] = p1.y;
            pd16[jj * 8 + 6] = p1.z; pd16[jj * 8 + 7] = p1.w;
            ws16[jj * 8 + 0] = w0.x; ws16[jj * 8 + 1] = w0.y;
            ws16[jj * 8 + 2] = w0.z; ws16[jj * 8 + 3] = w0.w;
            ws16[jj * 8 + 4] = w1.x; ws16[jj * 8 + 5] = w1.y;
            ws16[jj * 8 + 6] = w1.z; ws16[jj * 8 + 7] = w1.w;
        }
    }
    // 8 warps x 4 t's
#pragma unroll
    for (int it = 0; it < 4; it++) {
        int t = tc * 32 + warp * 4 + it;
        const uint4* row = (const uint4*)(g_peh + ((size_t)b * TE + t) * HH);
        float acc = 0.0f;
#pragma unroll
        for (int jj = 0; jj < 2; jj++) {
            uint4 v = row[lane + 32 * jj];
            const float* pd = &pd16[jj * 8];
            const float* ws = &ws16[jj * 8];
            float2 f;
            f = __half22float2(*(__half2*)&v.x);
            acc += ws[0] * fast_tanh(pd[0] + f.x) + ws[1] * fast_tanh(pd[1] + f.y);
            f = __half22float2(*(__half2*)&v.y);
            acc += ws[2] * fast_tanh(pd[2] + f.x) + ws[3] * fast_tanh(pd[3] + f.y);
            f = __half22float2(*(__half2*)&v.z);
            acc += ws[4] * fast_tanh(pd[4] + f.x) + ws[5] * fast_tanh(pd[5] + f.y);
            f = __half22float2(*(__half2*)&v.w);
            acc += ws[6] * fast_tanh(pd[6] + f.x) + ws[7] * fast_tanh(pd[7] + f.y);
        }
#pragma unroll
        for (int off = 16; off > 0; off >>= 1)
            acc += __shfl_down_sync(0xffffffffu, acc, off);
        if (lane == 0) g_e[b * TE + t] = acc;
    }
}

// ---------------- B2: softmax + context for batch b ----------------
__device__ __noinline__ void attn_ctx(int b, const float* __restrict__ h_en, SmemA& a) {
    const int tid = threadIdx.x;
    __syncthreads();
    float ev = g_e[b * TE + tid];
    a.red[tid] = ev;
    __syncthreads();
    for (int s = 128; s > 0; s >>= 1) {
        if (tid < s) a.red[tid] = fmaxf(a.red[tid], a.red[tid + s]);
        __syncthreads();
    }
    float mx = a.red[0];
    __syncthreads();
    float p = __expf(ev - mx);
    a.red[tid] = p;
    __syncthreads();
    for (int s = 128; s > 0; s >>= 1) {
        if (tid < s) a.red[tid] += a.red[tid + s];
        __syncthreads();
    }
    float inv = 1.0f / a.red[0];
    a.ss[tid] = p * inv;
    __syncthreads();
    for (int m = tid; m < HH; m += NTHR) {
        const float* hb = h_en + (size_t)b * TE * HH + m;
        float a0 = 0, a1 = 0, a2 = 0, a3 = 0;
        for (int t = 0; t < TE; t += 4) {
            a0 += a.ss[t + 0] * hb[(size_t)(t + 0) * HH];
            a1 += a.ss[t + 1] * hb[(size_t)(t + 1) * HH];
            a2 += a.ss[t + 2] * hb[(size_t)(t + 2) * HH];
            a3 += a.ss[t + 3] * hb[(size_t)(t + 3) * HH];
        }
        g_ctx[b * HH + m] = (a0 + a1) + (a2 + a3);
    }
}

// ---------------- weight packing (also zeroes the barrier counter) ----------------
__global__ void k_pack(const float* __restrict__ W_ih, const float* __restrict__ W_hh,
                       const float* __restrict__ W_ff1, const float* __restrict__ W_ff2,
                       const float* __restrict__ W_ta, const float* __restrict__ W_tb,
                       const float* __restrict__ b_ff1, const float* __restrict__ b_ff2,
                       const float* __restrict__ b_ta, const float* __restrict__ b_tb) {
    if (blockIdx.x == 0 && threadIdx.x == 0) g_arr = 0ull;
    const int N6 = G4 * CAT;
    const int N3 = 3 * HH * CAT;
    const int NB2 = 3 * HH;
    int total = N6 + N3 + NB2;
    for (int i = blockIdx.x * blockDim.x + threadIdx.x; i < total; i += gridDim.x * blockDim.x) {
        if (i < N6) {
            int nn = i / CAT, k = i % CAT;
            g_w6[i] = (k < CIN) ? W_ih[nn * CIN + k] : W_hh[nn * HH + (k - CIN)];
        } else if (i < N6 + N3) {
            int j = i - N6;
            int nn = j / CAT, k = j % CAT;
            int gate = nn / HH, u = nn % HH;
            float v;
            if (gate == 0)      v = W_ff1[u * CAT + k];
            else if (gate == 1) v = W_ff2[u * CAT + k];
            else                v = W_ta[u * CAT + k] + W_tb[u * CAT + k];
            g_w3[j] = v;
        } else {
            int nn = i - N6 - N3;
            int gate = nn / HH, u = nn % HH;
            g_b3[nn] = (gate == 0) ? b_ff1[u] : (gate == 1) ? b_ff2[u] : (b_ta[u] + b_tb[u]);
        }
    }
}

// ---------------- the persistent uber-kernel ----------------
__global__ void __launch_bounds__(NTHR, 2)
k_main(const float* __restrict__ x, const float* __restrict__ h_en,
       const float* __restrict__ W_dec, const float* __restrict__ W_enc,
       const float* __restrict__ b_enc, const float* __restrict__ w_score,
       const float* __restrict__ W_yattn, const float* __restrict__ b_yattn,
       const float* __restrict__ b_ih,
       const float* __restrict__ W_o1, const float* __restrict__ b_o1,
       const float* __restrict__ W_o2, const float* __restrict__ b_o2,
       float* __restrict__ out, int write_state) {
    __shared__ Smem sm;
    const int bid = blockIdx.x;
    const int tid = threadIdx.x;
    const int gstep = NBLK * NTHR;
    unsigned long long bar_t = 0;

    // ---- P0: init h,c + proj_enc -> fp16 ----
    for (int idx = bid * NTHR + tid; idx < BB * HH; idx += gstep) {
        g_h[idx] = 0.0f; g_c[idx] = 0.0f;
    }
    for (int j = bid; j < 2048; j += NBLK) {
        int mt = j >> 3, nt = j & 7;
        gemm64(h_en + (size_t)mt * 64 * HH, HH, HH, h_en, 0,
               W_enc, HH, nt * 64, 0, HH,
               nullptr, HH, b_enc, sm.g, g_peh + (size_t)mt * 64 * HH);
    }
    GSYNC();

    for (int t = 0; t < LL; t++) {
        const float* xt = x + (size_t)t * CIN;
        // ---- A: pd (8nt x 16ks = 128) + zh nt 0..19 (160) = 288 jobs ----
        for (int j = bid; j < 288; j += NBLK) {
            if (j < 128) {
                int nt = j >> 4, ks = j & 15;
                gemm64(g_h, HH, HH, g_c, HH,
                       W_dec, 1024, nt * 64, ks * 64, 64,
                       g_pdp + (size_t)ks * 64 * HH, HH, nullptr, sm.g, nullptr);
            } else {
                int q = j - 128;
                int nt = q >> 3, ks = q & 7;
                gemm64(g_h, CIN, 0, g_h, HH,
                       g_w6, CAT, nt * 64, CIN + ks * 64, 64,
                       g_zp + (size_t)ks * 64 * G4, G4, nullptr, sm.g, nullptr);
            }
        }
        GSYNC();
        // ---- B1: e-scores spread over all blocks (64 b x 8 tc = 512 jobs) ----
        for (int j = bid; j < 512; j += NBLK) {
            escore(j >> 3, j & 7, w_score, sm.a);
        }
        GSYNC();
        // ---- B2: softmax+ctx (blocks 0-63) || zh nt 20..31 (96) + xx (16) ----
        if (bid < 64) {
            attn_ctx(bid, h_en, sm.a);
        } else {
            for (int j = bid - 64; j < 112; j += NBLK - 64) {
                if (j < 96) {
                    int nt = 20 + (j >> 3), ks = j & 7;
                    gemm64(g_h, CIN, 0, g_h, HH,
                           g_w6, CAT, nt * 64, CIN + ks * 64, 64,
                           g_zp + (size_t)ks * 64 * G4, G4, nullptr, sm.g, nullptr);
                } else {
                    int q = j - 96;
                    int nt = q >> 2, ks = q & 3;
                    gemm64(xt, CIN, LL * CIN, xt, 0,
                           W_yattn, CAT, nt * 64, ks * 64, 64,
                           g_xp + (size_t)ks * 64 * CIN, CIN, nullptr, sm.g, nullptr);
                }
            }
        }
        GSYNC();
        // ---- C: xc (4nt x 8ks = 32 jobs -> xp slices 4..11) ----
        for (int j = bid; j < 32; j += NBLK) {
            int nt = j >> 3, ks = j & 7;
            gemm64(xt, CIN, LL * CIN, g_ctx, HH,
                   W_yattn, CAT, nt * 64, CIN + ks * 64, 64,
                   g_xp + (size_t)(4 + ks) * 64 * CIN, CIN, nullptr, sm.g, nullptr);
        }
        GSYNC();
        // ---- C2: reduce xhat (12 slices) + bias ----
        for (int idx = bid * NTHR + tid; idx < BB * CIN; idx += gstep) {
            int m = idx >> 8, nn = idx & 255;
            float s = b_yattn[nn];
#pragma unroll
            for (int sl = 0; sl < 12; sl++)
                s += g_xp[(size_t)(sl * 64 + m) * CIN + nn];
            g_xhat[idx] = s;
        }
        GSYNC();
        // ---- D: zx (128, zp 8-11) + cfcx (96, fp 8-11) ----
        for (int j = bid; j < 224; j += NBLK) {
            if (j < 128) {
                int nt = j >> 2, ks = j & 3;
                gemm64(g_xhat, CIN, CIN, g_xhat, 0,
                       g_w6, CAT, nt * 64, ks * 64, 64,
                       g_zp + (size_t)(8 + ks) * 64 * G4, G4, nullptr, sm.g, nullptr);
            } else {
                int q = j - 128;
                int nt = q >> 2, ks = q & 3;
                gemm64(g_xhat, CIN, CIN, g_xhat, 0,
                       g_w3, CAT, nt * 64, ks * 64, 64,
                       g_fp + (size_t)(8 + ks) * 64 * (3 * HH), 3 * HH, nullptr, sm.g, nullptr);
            }
        }
        GSYNC();
        // ---- E: LSTM pointwise (fold zp slices 0-11) ----
        for (int idx = bid * NTHR + tid; idx < BB * HH; idx += gstep) {
            int m = idx >> 9, u = idx & 511;
            float zi = b_ih[u], zg = b_ih[u + 512], zf = b_ih[u + 1024], zo = b_ih[u + 1536];
#pragma unroll
            for (int sl = 0; sl < 12; sl++) {
                const float* p = g_zp + (size_t)(sl * 64 + m) * G4;
                zi += p[u]; zg += p[u + 512]; zf += p[u + 1024]; zo += p[u + 1536];
            }
            float c_old = g_c[idx];
            float nc = c_old * sigm(zf + 1.0f) + tanhf(zi) * sigm(zg);
            g_c[idx] = nc;
            g_hlstm[idx] = tanhf(nc) * sigm(zo);
        }
        GSYNC();
        // ---- F: cfc h-part (192, fp slices 0-7) ----
        for (int j = bid; j < 192; j += NBLK) {
            int nt = j >> 3, ks = j & 7;
            gemm64(g_hlstm, CIN, 0, g_hlstm, HH,
                   g_w3, CAT, nt * 64, CIN + ks * 64, 64,
                   g_fp + (size_t)ks * 64 * (3 * HH), 3 * HH, nullptr, sm.g, nullptr);
        }
        GSYNC();
        // ---- G: CfC pointwise (fold fp slices 0-11) -> new h ----
        for (int idx = bid * NTHR + tid; idx < BB * HH; idx += gstep) {
            int m = idx >> 9, u = idx & 511;
            float f1 = g_b3[u], f2 = g_b3[u + 512], tg = g_b3[u + 1024];
#pragma unroll
            for (int sl = 0; sl < 12; sl++) {
                const float* p = g_fp + (size_t)(sl * 64 + m) * (3 * HH);
                f1 += p[u]; f2 += p[u + 512]; tg += p[u + 1024];
            }
            float ti = sigm(tg);
            g_h[idx] = tanhf(f1) * (1.0f - ti) + ti * tanhf(f2);
        }
        GSYNC();
    }

    // ---- E1: O1 GEMM ([h|ctx], K=1024): 128 jobs -> zp (stride HH) ----
    for (int j = bid; j < 128; j += NBLK) {
        int nt = j >> 4, ks = j & 15;
        gemm64(g_h, HH, HH, g_ctx, HH,
               W_o1, 1024, nt * 64, ks * 64, 64,
               g_zp + (size_t)ks * 64 * HH, HH, nullptr, sm.g, nullptr);
    }
    GSYNC();
    // ---- E2: reduce 16 + leaky relu -> g_hid ----
    for (int idx = bid * NTHR + tid; idx < BB * HH; idx += gstep) {
        int m = idx >> 9, u = idx & 511;
        float s = b_o1[u];
#pragma unroll
        for (int sl = 0; sl < 16; sl++)
            s += g_zp[(size_t)(sl * 64 + m) * HH + u];
        g_hid[idx] = (s > 0.0f) ? s : 0.01f * s;
    }
    GSYNC();
    // ---- E3: O2 GEMM (hid, K=512): 16 jobs -> fp (stride OUTN) ----
    for (int j = bid; j < 16; j += NBLK) {
        int nt = j >> 3, ks = j & 7;
        gemm64(g_hid, HH, HH, g_hid, 0,
               W_o2, HH, nt * 64, ks * 64, 64,
               g_fp + (size_t)ks * 64 * OUTN, OUTN, nullptr, sm.g, nullptr);
    }
    GSYNC();
    // ---- E4: final reduce + bias (+ optional state copy) ----
    for (int idx = bid * NTHR + tid; idx < BB * OUTN; idx += gstep) {
        int m = idx >> 7, u = idx & 127;
        float s = b_o2[u];
#pragma unroll
        for (int sl = 0; sl < 8; sl++)
            s += g_fp[(size_t)(sl * 64 + m) * OUTN + u];
        out[idx] = s;
    }
    if (write_state) {
        for (int idx = bid * NTHR + tid; idx < BB * HH; idx += gstep) {
            out[BB * OUTN + idx] = g_h[idx];
            out[BB * OUTN + BB * HH + idx] = g_c[idx];
        }
    }
}

// ============================================================================
extern "C" void kernel_launch(void* const* d_in, const int* in_sizes, int n_in,
                              void* d_out, int out_size) {
    const float* x       = (const float*)d_in[0];
    const float* h_en    = (const float*)d_in[1];
    const float* W_dec   = (const float*)d_in[2];
    const float* W_enc   = (const float*)d_in[3];
    const float* b_enc   = (const float*)d_in[4];
    const float* w_score = (const float*)d_in[5];
    const float* W_yattn = (const float*)d_in[6];
    const float* b_yattn = (const float*)d_in[7];
    const float* W_ih    = (const float*)d_in[8];
    const float* b_ih    = (const float*)d_in[9];
    const float* W_hh    = (const float*)d_in[10];
    const float* W_ff1   = (const float*)d_in[11];
    const float* b_ff1   = (const float*)d_in[12];
    const float* W_ff2   = (const float*)d_in[13];
    const float* b_ff2   = (const float*)d_in[14];
    const float* W_ta    = (const float*)d_in[15];
    const float* b_ta    = (const float*)d_in[16];
    const float* W_tb    = (const float*)d_in[17];
    const float* b_tb    = (const float*)d_in[18];
    const float* W_o1    = (const float*)d_in[19];
    const float* b_o1    = (const float*)d_in[20];
    const float* W_o2    = (const float*)d_in[21];
    const float* b_o2    = (const float*)d_in[22];
    float* out = (float*)d_out;

    int write_state = (out_size >= BB * OUTN + 2 * BB * HH) ? 1 : 0;

    k_pack<<<512, 256>>>(W_ih, W_hh, W_ff1, W_ff2, W_ta, W_tb,
                         b_ff1, b_ff2, b_ta, b_tb);
    k_main<<<NBLK, NTHR>>>(x, h_en, W_dec, W_enc, b_enc, w_score,
                           W_yattn, b_yattn, b_ih, W_o1, b_o1, W_o2, b_o2,
                           out, write_state);
}

// round 11
// speedup vs baseline: 2.0298x; 1.3355x over previous
#include <cuda_runtime.h>
#include <cuda_fp16.h>
#include <cstdint>

#define BB   64
#define LL   128
#define TE   256
#define CIN  256
#define HH   512
#define CAT  768
#define G4   2048
#define OUTN 128
#define NBLK 288
#define NTHR 256

// ---------------- persistent device buffers ----------------
__device__ __half g_peh[(size_t)BB * TE * HH];   // proj_enc fp16 (16 MB)
__device__ __half g_henh[(size_t)BB * TE * HH];  // h_en fp16 (16 MB)
__device__ __half g_xh[(size_t)BB * LL * CIN];   // x fp16 (4 MB)
__device__ float g_e[BB * TE];
__device__ float g_pdp[16 * 64 * HH];            // pd partials (16 slices)
__device__ float g_xp[12 * 64 * CIN];            // xhat partials (xx:0-3, xc:4-11)
__device__ float g_zp[16 * 64 * G4];             // z partials (zh:0-7, zx:8-11; epi O1)
__device__ float g_fp[12 * 64 * 3 * HH];         // cfc partials (h:0-7, x:8-11; epi O2)
__device__ float g_h[BB * HH];
__device__ float g_c[BB * HH];
__device__ float g_ctx[BB * HH];
// fp16 activation twins (GEMM A operands)
__device__ __half g_hh[BB * HH];
__device__ __half g_ch[BB * HH];
__device__ __half g_ctxh[BB * HH];
__device__ __half g_xhath[BB * CIN];
__device__ __half g_hlh[BB * HH];
__device__ __half g_hidh[BB * HH];
// fp16 weights
__device__ __half g_w6h[G4 * CAT];               // [W_ih | W_hh]
__device__ __half g_w3h[3 * HH * CAT];           // [ff1; ff2; ta+tb]
__device__ __half g_wdh[HH * 1024];              // W_dec
__device__ __half g_wyh[CIN * CAT];              // W_yattn
__device__ __half g_wo1h[HH * 1024];             // W_o1
__device__ __half g_wo2h[OUTN * HH];             // W_o2
__device__ __half g_wench[HH * HH];              // W_enc
__device__ float g_b3[3 * HH];
__device__ unsigned long long g_arr;             // monotonic barrier counter

// ---------------- helpers ----------------
__device__ __forceinline__ float fast_tanh(float x) {
    float y;
    asm("tanh.approx.f32 %0, %1;" : "=f"(y) : "f"(x));
    return y;
}
__device__ __forceinline__ float sigm(float x) {
    return 1.0f / (1.0f + __expf(-x));
}

// ---------------- fast global barrier (monotonic counter) ----------------
#define GSYNC() do {                                                     \
    __syncthreads();                                                     \
    if (threadIdx.x == 0) {                                              \
        __threadfence();                                                 \
        bar_t += NBLK;                                                   \
        atomicAdd(&g_arr, 1ull);                                         \
        while (*(volatile unsigned long long*)&g_arr < bar_t) { }        \
        __threadfence();                                                 \
    }                                                                    \
    __syncthreads();                                                     \
} while (0)

// ---------------- shared memory ----------------
struct SmemA { float pds[HH]; float wss[HH]; float ss[TE]; float red[NTHR]; };

// ---------------- mma.sync m16n8k16 fp16 -> fp32 ----------------
__device__ __forceinline__ void mma16816(float* c, unsigned a0, unsigned a1,
                                         unsigned a2, unsigned a3,
                                         unsigned b0, unsigned b1) {
    asm volatile(
        "mma.sync.aligned.m16n8k16.row.col.f32.f16.f16.f32 "
        "{%0,%1,%2,%3}, {%4,%5,%6,%7}, {%8,%9}, {%0,%1,%2,%3};"
        : "+f"(c[0]), "+f"(c[1]), "+f"(c[2]), "+f"(c[3])
        : "r"(a0), "r"(a1), "r"(a2), "r"(a3), "r"(b0), "r"(b1));
}

// ---------------- 64x64xK GEMM job, 256 threads, tensor-core, no smem ----------
// A fp16 row-major (64 x klen, leading dim lda), W fp16 row-major (64 x klen,
// leading dim ldw) -- W rows are output cols. dst fp32 (or dsth fp16) 64x64,
// leading dim dstr. bias (or null) indexed by local col. klen % 16 == 0.
__device__ __noinline__ void gemm_mma(const __half* __restrict__ A, int lda,
                                      const __half* __restrict__ W, int ldw,
                                      int klen,
                                      float* __restrict__ dst, int dstr,
                                      __half* __restrict__ dsth,
                                      const float* __restrict__ bias) {
    const int tid  = threadIdx.x;
    const int lane = tid & 31, wid = tid >> 5;
    const int wm = wid >> 1, wn = wid & 1;      // 4 x 2 warp grid -> m16 x n32
    const int gr = lane >> 2, kc = (lane & 3) * 2;
    float c[4][4];
#pragma unroll
    for (int nf = 0; nf < 4; nf++)
#pragma unroll
        for (int i = 0; i < 4; i++) c[nf][i] = 0.0f;

    const __half* Ab = A + (size_t)(wm * 16 + gr) * lda + kc;
    const __half* Wb = W + (size_t)(wn * 32 + gr) * ldw + kc;
#pragma unroll 4
    for (int k0 = 0; k0 < klen; k0 += 16) {
        unsigned a0 = *(const unsigned*)(Ab + k0);
        unsigned a1 = *(const unsigned*)(Ab + 8 * lda + k0);
        unsigned a2 = *(const unsigned*)(Ab + k0 + 8);
        unsigned a3 = *(const unsigned*)(Ab + 8 * lda + k0 + 8);
#pragma unroll
        for (int nf = 0; nf < 4; nf++) {
            const __half* Br = Wb + (size_t)(nf * 8) * ldw + k0;
            unsigned b0 = *(const unsigned*)(Br);
            unsigned b1 = *(const unsigned*)(Br + 8);
            mma16816(c[nf], a0, a1, a2, a3, b0, b1);
        }
    }
    const int row = wm * 16 + gr;
#pragma unroll
    for (int nf = 0; nf < 4; nf++) {
        int col = wn * 32 + nf * 8 + kc;
        float add0 = 0.0f, add1 = 0.0f;
        if (bias) { add0 = bias[col]; add1 = bias[col + 1]; }
        float v0 = c[nf][0] + add0, v1 = c[nf][1] + add1;
        float v2 = c[nf][2] + add0, v3 = c[nf][3] + add1;
        if (dsth) {
            *(__half2*)(dsth + (size_t)row * dstr + col) = __floats2half2_rn(v0, v1);
            *(__half2*)(dsth + (size_t)(row + 8) * dstr + col) = __floats2half2_rn(v2, v3);
        } else {
            *(float2*)(dst + (size_t)row * dstr + col) = make_float2(v0, v1);
            *(float2*)(dst + (size_t)(row + 8) * dstr + col) = make_float2(v2, v3);
        }
    }
}

// ---------------- B1: e-scores for (batch b, t-chunk tc of 32) ----------------
__device__ __noinline__ void escore(int b, int tc, const float* __restrict__ w_score,
                                    SmemA& a) {
    const int tid = threadIdx.x;
    __syncthreads();
    for (int h = tid; h < HH; h += NTHR) {
        float sacc = 0.0f;
#pragma unroll
        for (int sl = 0; sl < 16; sl++)
            sacc += g_pdp[(size_t)(sl * 64 + b) * HH + h];
        a.pds[h] = sacc;
        a.wss[h] = w_score[h];
    }
    __syncthreads();
    const int warp = tid >> 5, lane = tid & 31;
    float pd16[16], ws16[16];
    {
        const float4* ps = (const float4*)a.pds;
        const float4* wsv = (const float4*)a.wss;
#pragma unroll
        for (int jj = 0; jj < 2; jj++) {
            int base = (lane + 32 * jj) * 2;
            float4 p0 = ps[base], p1 = ps[base + 1];
            float4 w0 = wsv[base], w1 = wsv[base + 1];
            pd16[jj * 8 + 0] = p0.x; pd16[jj * 8 + 1] = p0.y;
            pd16[jj * 8 + 2] = p0.z; pd16[jj * 8 + 3] = p0.w;
            pd16[jj * 8 + 4] = p1.x; pd16[jj * 8 + 5] = p1.y;
            pd16[jj * 8 + 6] = p1.z; pd16[jj * 8 + 7] = p1.w;
            ws16[jj * 8 + 0] = w0.x; ws16[jj * 8 + 1] = w0.y;
            ws16[jj * 8 + 2] = w0.z; ws16[jj * 8 + 3] = w0.w;
            ws16[jj * 8 + 4] = w1.x; ws16[jj * 8 + 5] = w1.y;
            ws16[jj * 8 + 6] = w1.z; ws16[jj * 8 + 7] = w1.w;
        }
    }
#pragma unroll
    for (int it = 0; it < 4; it++) {
        int t = tc * 32 + warp * 4 + it;
        const uint4* row = (const uint4*)(g_peh + ((size_t)b * TE + t) * HH);
        float acc = 0.0f;
#pragma unroll
        for (int jj = 0; jj < 2; jj++) {
            uint4 v = row[lane + 32 * jj];
            const float* pd = &pd16[jj * 8];
            const float* ws = &ws16[jj * 8];
            float2 f;
            f = __half22float2(*(__half2*)&v.x);
            acc += ws[0] * fast_tanh(pd[0] + f.x) + ws[1] * fast_tanh(pd[1] + f.y);
            f = __half22float2(*(__half2*)&v.y);
            acc += ws[2] * fast_tanh(pd[2] + f.x) + ws[3] * fast_tanh(pd[3] + f.y);
            f = __half22float2(*(__half2*)&v.z);
            acc += ws[4] * fast_tanh(pd[4] + f.x) + ws[5] * fast_tanh(pd[5] + f.y);
            f = __half22float2(*(__half2*)&v.w);
            acc += ws[6] * fast_tanh(pd[6] + f.x) + ws[7] * fast_tanh(pd[7] + f.y);
        }
#pragma unroll
        for (int off = 16; off > 0; off >>= 1)
            acc += __shfl_down_sync(0xffffffffu, acc, off);
        if (lane == 0) g_e[b * TE + t] = acc;
    }
}

// ---------------- B2: softmax (recomputed) + context quarter ----------------
// job (b, qm): computes ctx[b, qm*128 .. qm*128+127]
__device__ __noinline__ void ctx_job(int b, int qm, const float* __restrict__ h_en,
                                     SmemA& a) {
    const int tid = threadIdx.x;
    __syncthreads();
    float ev = g_e[b * TE + tid];
    a.red[tid] = ev;
    __syncthreads();
    for (int s = 128; s > 0; s >>= 1) {
        if (tid < s) a.red[tid] = fmaxf(a.red[tid], a.red[tid + s]);
        __syncthreads();
    }
    float mx = a.red[0];
    __syncthreads();
    float p = __expf(ev - mx);
    a.red[tid] = p;
    __syncthreads();
    for (int s = 128; s > 0; s >>= 1) {
        if (tid < s) a.red[tid] += a.red[tid + s];
        __syncthreads();
    }
    float inv = 1.0f / a.red[0];
    a.ss[tid] = p * inv;
    __syncthreads();
    const int ml = tid & 127, th = tid >> 7;
    const int m = qm * 128 + ml;
    const float* hb = h_en + ((size_t)b * TE + th * 128) * HH + m;
    const float* ssp = &a.ss[th * 128];
    float a0 = 0, a1 = 0, a2 = 0, a3 = 0;
#pragma unroll 4
    for (int t = 0; t < 128; t += 4) {
        a0 += ssp[t + 0] * hb[(size_t)(t + 0) * HH];
        a1 += ssp[t + 1] * hb[(size_t)(t + 1) * HH];
        a2 += ssp[t + 2] * hb[(size_t)(t + 2) * HH];
        a3 += ssp[t + 3] * hb[(size_t)(t + 3) * HH];
    }
    __syncthreads();
    a.red[tid] = (a0 + a1) + (a2 + a3);
    __syncthreads();
    if (th == 0) {
        float v = a.red[tid] + a.red[tid + 128];
        g_ctx[b * HH + m] = v;
        g_ctxh[b * HH + m] = __float2half_rn(v);
    }
}

// ---------------- prologue pack kernel (weights->fp16, x/h_en->fp16) ----------
__global__ void k_pack(const float* __restrict__ x, const float* __restrict__ h_en,
                       const float* __restrict__ W_dec, const float* __restrict__ W_enc,
                       const float* __restrict__ W_yattn,
                       const float* __restrict__ W_ih, const float* __restrict__ W_hh,
                       const float* __restrict__ W_ff1, const float* __restrict__ W_ff2,
                       const float* __restrict__ W_ta, const float* __restrict__ W_tb,
                       const float* __restrict__ b_ff1, const float* __restrict__ b_ff2,
                       const float* __restrict__ b_ta, const float* __restrict__ b_tb,
                       const float* __restrict__ W_o1, const float* __restrict__ W_o2) {
    if (blockIdx.x == 0 && threadIdx.x == 0) g_arr = 0ull;
    const int N1 = G4 * CAT;            // w6h
    const int N2 = 3 * HH * CAT;        // w3h
    const int N3 = 3 * HH;              // b3
    const int N4 = HH * 1024;           // wdh
    const int N5 = CIN * CAT;           // wyh
    const int N6 = HH * 1024;           // wo1h
    const int N7 = OUTN * HH;           // wo2h
    const int N8 = HH * HH;             // wench
    const int N9 = BB * LL * CIN;       // xh
    const int N10 = BB * TE * HH;       // henh
    const int T1 = N1, T2 = T1 + N2, T3 = T2 + N3, T4 = T3 + N4, T5 = T4 + N5;
    const int T6 = T5 + N6, T7 = T6 + N7, T8 = T7 + N8, T9 = T8 + N9;
    const int total = T9 + N10;
    for (int i = blockIdx.x * blockDim.x + threadIdx.x; i < total;
         i += gridDim.x * blockDim.x) {
        if (i < T1) {
            int nn = i / CAT, k = i % CAT;
            float v = (k < CIN) ? W_ih[nn * CIN + k] : W_hh[nn * HH + (k - CIN)];
            g_w6h[i] = __float2half_rn(v);
        } else if (i < T2) {
            int j = i - T1;
            int nn = j / CAT, k = j % CAT;
            int gate = nn / HH, u = nn % HH;
            float v;
            if (gate == 0)      v = W_ff1[u * CAT + k];
            else if (gate == 1) v = W_ff2[u * CAT + k];
            else                v = W_ta[u * CAT + k] + W_tb[u * CAT + k];
            g_w3h[j] = __float2half_rn(v);
        } else if (i < T3) {
            int nn = i - T2;
            int gate = nn / HH, u = nn % HH;
            g_b3[nn] = (gate == 0) ? b_ff1[u] : (gate == 1) ? b_ff2[u]
                                              : (b_ta[u] + b_tb[u]);
        } else if (i < T4) {
            int j = i - T3;
            g_wdh[j] = __float2half_rn(W_dec[j]);
        } else if (i < T5) {
            int j = i - T4;
            g_wyh[j] = __float2half_rn(W_yattn[j]);
        } else if (i < T6) {
            int j = i - T5;
            g_wo1h[j] = __float2half_rn(W_o1[j]);
        } else if (i < T7) {
            int j = i - T6;
            g_wo2h[j] = __float2half_rn(W_o2[j]);
        } else if (i < T8) {
            int j = i - T7;
            g_wench[j] = __float2half_rn(W_enc[j]);
        } else if (i < T9) {
            int j = i - T8;
            g_xh[j] = __float2half_rn(x[j]);
        } else {
            int j = i - T9;
            g_henh[j] = __float2half_rn(h_en[j]);
        }
    }
}

// ---------------- the persistent uber-kernel ----------------
__global__ void __launch_bounds__(NTHR, 2)
k_main(const float* __restrict__ h_en,
       const float* __restrict__ b_enc, const float* __restrict__ w_score,
       const float* __restrict__ b_yattn, const float* __restrict__ b_ih,
       const float* __restrict__ b_o1, const float* __restrict__ b_o2,
       float* __restrict__ out, int write_state) {
    __shared__ SmemA sa;
    const int bid = blockIdx.x;
    const int tid = threadIdx.x;
    const int gstep = NBLK * NTHR;
    unsigned long long bar_t = 0;

    // ---- P0: init states + proj_enc -> fp16 (full K=512 per job) ----
    for (int idx = bid * NTHR + tid; idx < BB * HH; idx += gstep) {
        g_h[idx] = 0.0f; g_c[idx] = 0.0f;
        g_hh[idx] = __float2half_rn(0.0f);
        g_ch[idx] = __float2half_rn(0.0f);
    }
    for (int j = bid; j < 2048; j += NBLK) {
        int mt = j >> 3, nt = j & 7;
        gemm_mma(g_henh + (size_t)mt * 64 * HH, HH,
                 g_wench + (size_t)(nt * 64) * HH, HH, HH,
                 nullptr, HH, g_peh + (size_t)mt * 64 * HH + nt * 64,
                 b_enc + nt * 64);
    }
    GSYNC();

    for (int t = 0; t < LL; t++) {
        // ---- A: pd(128) + zh(256) + xx(16) = 400 jobs ----
        for (int j = bid; j < 400; j += NBLK) {
            if (j < 128) {
                int nt = j >> 4, ks = j & 15;
                const __half* A = (ks < 8) ? g_hh + ks * 64 : g_ch + (ks - 8) * 64;
                gemm_mma(A, HH, g_wdh + (size_t)(nt * 64) * 1024 + ks * 64, 1024, 64,
                         g_pdp + (size_t)ks * 64 * HH + nt * 64, HH, nullptr, nullptr);
            } else if (j < 384) {
                int q = j - 128;
                int nt = q >> 3, ks = q & 7;
                gemm_mma(g_hh + ks * 64, HH,
                         g_w6h + (size_t)(nt * 64) * CAT + CIN + ks * 64, CAT, 64,
                         g_zp + (size_t)ks * 64 * G4 + nt * 64, G4, nullptr, nullptr);
            } else {
                int q = j - 384;
                int nt = q >> 2, ks = q & 3;
                gemm_mma(g_xh + (size_t)t * CIN + ks * 64, LL * CIN,
                         g_wyh + (size_t)(nt * 64) * CAT + ks * 64, CAT, 64,
                         g_xp + (size_t)ks * 64 * CIN + nt * 64, CIN, nullptr, nullptr);
            }
        }
        GSYNC();
        // ---- B1: e-scores (512 light jobs) ----
        for (int j = bid; j < 512; j += NBLK) {
            escore(j >> 3, j & 7, w_score, sa);
        }
        GSYNC();
        // ---- B2: softmax + ctx quarters (256 jobs) ----
        for (int j = bid; j < 256; j += NBLK) {
            ctx_job(j >> 2, j & 3, h_en, sa);
        }
        GSYNC();
        // ---- C: xc (32 jobs -> xp slices 4..11) ----
        for (int j = bid; j < 32; j += NBLK) {
            int nt = j >> 3, ks = j & 7;
            gemm_mma(g_ctxh + ks * 64, HH,
                     g_wyh + (size_t)(nt * 64) * CAT + CIN + ks * 64, CAT, 64,
                     g_xp + (size_t)(4 + ks) * 64 * CIN + nt * 64, CIN, nullptr, nullptr);
        }
        GSYNC();
        // ---- C2: reduce xhat (12 slices) + bias -> fp16 ----
        for (int idx = bid * NTHR + tid; idx < BB * CIN; idx += gstep) {
            int m = idx >> 8, nn = idx & 255;
            float s = b_yattn[nn];
#pragma unroll
            for (int sl = 0; sl < 12; sl++)
                s += g_xp[(size_t)(sl * 64 + m) * CIN + nn];
            g_xhath[idx] = __float2half_rn(s);
        }
        GSYNC();
        // ---- D: zx(128 -> zp 8-11) + cfcx(96 -> fp 8-11) ----
        for (int j = bid; j < 224; j += NBLK) {
            if (j < 128) {
                int nt = j >> 2, ks = j & 3;
                gemm_mma(g_xhath + ks * 64, CIN,
                         g_w6h + (size_t)(nt * 64) * CAT + ks * 64, CAT, 64,
                         g_zp + (size_t)(8 + ks) * 64 * G4 + nt * 64, G4, nullptr, nullptr);
            } else {
                int q = j - 128;
                int nt = q >> 2, ks = q & 3;
                gemm_mma(g_xhath + ks * 64, CIN,
                         g_w3h + (size_t)(nt * 64) * CAT + ks * 64, CAT, 64,
                         g_fp + (size_t)(8 + ks) * 64 * (3 * HH) + nt * 64, 3 * HH,
                         nullptr, nullptr);
            }
        }
        GSYNC();
        // ---- E: LSTM pointwise (fold zp 0-11) ----
        for (int idx = bid * NTHR + tid; idx < BB * HH; idx += gstep) {
            int m = idx >> 9, u = idx & 511;
            float zi = b_ih[u], zg = b_ih[u + 512], zf = b_ih[u + 1024], zo = b_ih[u + 1536];
#pragma unroll
            for (int sl = 0; sl < 12; sl++) {
                const float* p = g_zp + (size_t)(sl * 64 + m) * G4;
                zi += p[u]; zg += p[u + 512]; zf += p[u + 1024]; zo += p[u + 1536];
            }
            float c_old = g_c[idx];
            float nc = c_old * sigm(zf + 1.0f) + tanhf(zi) * sigm(zg);
            g_c[idx] = nc;
            g_ch[idx] = __float2half_rn(nc);
            float hl = tanhf(nc) * sigm(zo);
            g_hlh[idx] = __float2half_rn(hl);
        }
        GSYNC();
        // ---- F: cfc h-part (192 -> fp 0-7) ----
        for (int j = bid; j < 192; j += NBLK) {
            int nt = j >> 3, ks = j & 7;
            gemm_mma(g_hlh + ks * 64, HH,
                     g_w3h + (size_t)(nt * 64) * CAT + CIN + ks * 64, CAT, 64,
                     g_fp + (size_t)ks * 64 * (3 * HH) + nt * 64, 3 * HH, nullptr, nullptr);
        }
        GSYNC();
        // ---- G: CfC pointwise (fold fp 0-11) -> new h ----
        for (int idx = bid * NTHR + tid; idx < BB * HH; idx += gstep) {
            int m = idx >> 9, u = idx & 511;
            float f1 = g_b3[u], f2 = g_b3[u + 512], tg = g_b3[u + 1024];
#pragma unroll
            for (int sl = 0; sl < 12; sl++) {
                const float* p = g_fp + (size_t)(sl * 64 + m) * (3 * HH);
                f1 += p[u]; f2 += p[u + 512]; tg += p[u + 1024];
            }
            float ti = sigm(tg);
            float nh = tanhf(f1) * (1.0f - ti) + ti * tanhf(f2);
            g_h[idx] = nh;
            g_hh[idx] = __float2half_rn(nh);
        }
        GSYNC();
    }

    // ---- E1: O1 GEMM ([h|ctx], K=1024): 128 jobs -> zp (stride HH) ----
    for (int j = bid; j < 128; j += NBLK) {
        int nt = j >> 4, ks = j & 15;
        const __half* A = (ks < 8) ? g_hh + ks * 64 : g_ctxh + (ks - 8) * 64;
        gemm_mma(A, HH, g_wo1h + (size_t)(nt * 64) * 1024 + ks * 64, 1024, 64,
                 g_zp + (size_t)ks * 64 * HH + nt * 64, HH, nullptr, nullptr);
    }
    GSYNC();
    // ---- E2: reduce 16 + leaky relu -> fp16 hid ----
    for (int idx = bid * NTHR + tid; idx < BB * HH; idx += gstep) {
        int m = idx >> 9, u = idx & 511;
        float s = b_o1[u];
#pragma unroll
        for (int sl = 0; sl < 16; sl++)
            s += g_zp[(size_t)(sl * 64 + m) * HH + u];
        g_hidh[idx] = __float2half_rn((s > 0.0f) ? s : 0.01f * s);
    }
    GSYNC();
    // ---- E3: O2 GEMM (hid, K=512): 16 jobs -> fp (stride OUTN) ----
    for (int j = bid; j < 16; j += NBLK) {
        int nt = j >> 3, ks = j & 7;
        gemm_mma(g_hidh + ks * 64, HH,
                 g_wo2h + (size_t)(nt * 64) * HH + ks * 64, HH, 64,
                 g_fp + (size_t)ks * 64 * OUTN + nt * 64, OUTN, nullptr, nullptr);
    }
    GSYNC();
    // ---- E4: final reduce + bias (+ optional state copy) ----
    for (int idx = bid * NTHR + tid; idx < BB * OUTN; idx += gstep) {
        int m = idx >> 7, u = idx & 127;
        float s = b_o2[u];
#pragma unroll
        for (int sl = 0; sl < 8; sl++)
            s += g_fp[(size_t)(sl * 64 + m) * OUTN + u];
        out[idx] = s;
    }
    if (write_state) {
        for (int idx = bid * NTHR + tid; idx < BB * HH; idx += gstep) {
            out[BB * OUTN + idx] = g_h[idx];
            out[BB * OUTN + BB * HH + idx] = g_c[idx];
        }
    }
}

// ============================================================================
extern "C" void kernel_launch(void* const* d_in, const int* in_sizes, int n_in,
                              void* d_out, int out_size) {
    const float* x       = (const float*)d_in[0];
    const float* h_en    = (const float*)d_in[1];
    const float* W_dec   = (const float*)d_in[2];
    const float* W_enc   = (const float*)d_in[3];
    const float* b_enc   = (const float*)d_in[4];
    const float* w_score = (const float*)d_in[5];
    const float* W_yattn = (const float*)d_in[6];
    const float* b_yattn = (const float*)d_in[7];
    const float* W_ih    = (const float*)d_in[8];
    const float* b_ih    = (const float*)d_in[9];
    const float* W_hh    = (const float*)d_in[10];
    const float* W_ff1   = (const float*)d_in[11];
    const float* b_ff1   = (const float*)d_in[12];
    const float* W_ff2   = (const float*)d_in[13];
    const float* b_ff2   = (const float*)d_in[14];
    const float* W_ta    = (const float*)d_in[15];
    const float* b_ta    = (const float*)d_in[16];
    const float* W_tb    = (const float*)d_in[17];
    const float* b_tb    = (const float*)d_in[18];
    const float* W_o1    = (const float*)d_in[19];
    const float* b_o1    = (const float*)d_in[20];
    const float* W_o2    = (const float*)d_in[21];
    const float* b_o2    = (const float*)d_in[22];
    float* out = (float*)d_out;

    int write_state = (out_size >= BB * OUTN + 2 * BB * HH) ? 1 : 0;

    k_pack<<<512, 256>>>(x, h_en, W_dec, W_enc, W_yattn, W_ih, W_hh,
                         W_ff1, W_ff2, W_ta, W_tb,
                         b_ff1, b_ff2, b_ta, b_tb, W_o1, W_o2);
    k_main<<<NBLK, NTHR>>>(h_en, b_enc, w_score, b_yattn, b_ih,
                           b_o1, b_o2, out, write_state);
}

// round 12
// speedup vs baseline: 2.3479x; 1.1567x over previous
#include <cuda_runtime.h>
#include <cuda_fp16.h>
#include <cstdint>

#define BB   64
#define LL   128
#define TE   256
#define CIN  256
#define HH   512
#define CAT  768
#define G4   2048
#define OUTN 128
#define NBLK 288
#define NTHR 256

// ---------------- persistent device buffers ----------------
__device__ __half g_peh[(size_t)BB * TE * HH];   // proj_enc fp16 (16 MB)
__device__ __half g_henh[(size_t)BB * TE * HH];  // h_en fp16 (16 MB)
__device__ __half g_xh[(size_t)BB * LL * CIN];   // x fp16 (4 MB)
__device__ float g_h2[(size_t)BB * TE * CIN];    // h_en @ Wy_ctx^T (16 MB fp32)
__device__ float g_e[BB * TE];
__device__ float g_pdp[8 * 64 * HH];             // pd partials (8 slices k128)
__device__ float g_xp[64 * CIN];                 // xx partial (1 slice K=256)
__device__ float g_zp[6 * 64 * G4];              // z partials (zh:0-3, zx:4-5; epi O1)
__device__ float g_fp[6 * 64 * 3 * HH];          // cfc partials (h:0-3, x:4-5; epi O2)
__device__ float g_h[BB * HH];
__device__ float g_c[BB * HH];
// fp16 activation twins (GEMM A operands)
__device__ __half g_hh[BB * HH];
__device__ __half g_ch[BB * HH];
__device__ __half g_ctxh[BB * HH];
__device__ __half g_xhath[BB * CIN];
__device__ __half g_hlh[BB * HH];
__device__ __half g_hidh[BB * HH];
// fp16 weights
__device__ __half g_w6h[G4 * CAT];               // [W_ih | W_hh]
__device__ __half g_w3h[3 * HH * CAT];           // [ff1; ff2; ta+tb]
__device__ __half g_wdh[HH * 1024];              // W_dec
__device__ __half g_wyh[CIN * CAT];              // W_yattn
__device__ __half g_wo1h[HH * 1024];             // W_o1
__device__ __half g_wo2h[OUTN * HH];             // W_o2
__device__ __half g_wench[HH * HH];              // W_enc
__device__ float g_b3[3 * HH];
__device__ unsigned long long g_arr;             // monotonic barrier counter

// ---------------- helpers ----------------
__device__ __forceinline__ float fast_tanh(float x) {
    float y;
    asm("tanh.approx.f32 %0, %1;" : "=f"(y) : "f"(x));
    return y;
}
__device__ __forceinline__ float sigm(float x) {
    return 1.0f / (1.0f + __expf(-x));
}

// ---------------- fast global barrier (monotonic counter) ----------------
#define GSYNC() do {                                                     \
    __syncthreads();                                                     \
    if (threadIdx.x == 0) {                                              \
        __threadfence();                                                 \
        bar_t += NBLK;                                                   \
        atomicAdd(&g_arr, 1ull);                                         \
        while (*(volatile unsigned long long*)&g_arr < bar_t) { }        \
        __threadfence();                                                 \
    }                                                                    \
    __syncthreads();                                                     \
} while (0)

// ---------------- shared memory ----------------
struct SmemA { float pds[HH]; float wss[HH]; float ss[TE]; float red[NTHR]; };

// ---------------- mma.sync m16n8k16 fp16 -> fp32 ----------------
__device__ __forceinline__ void mma16816(float* c, unsigned a0, unsigned a1,
                                         unsigned a2, unsigned a3,
                                         unsigned b0, unsigned b1) {
    asm volatile(
        "mma.sync.aligned.m16n8k16.row.col.f32.f16.f16.f32 "
        "{%0,%1,%2,%3}, {%4,%5,%6,%7}, {%8,%9}, {%0,%1,%2,%3};"
        : "+f"(c[0]), "+f"(c[1]), "+f"(c[2]), "+f"(c[3])
        : "r"(a0), "r"(a1), "r"(a2), "r"(a3), "r"(b0), "r"(b1));
}

// ---------------- 64x64xK GEMM job, 256 threads, tensor-core, no smem ----------
__device__ __noinline__ void gemm_mma(const __half* __restrict__ A, int lda,
                                      const __half* __restrict__ W, int ldw,
                                      int klen,
                                      float* __restrict__ dst, int dstr,
                                      __half* __restrict__ dsth,
                                      const float* __restrict__ bias) {
    const int tid  = threadIdx.x;
    const int lane = tid & 31, wid = tid >> 5;
    const int wm = wid >> 1, wn = wid & 1;      // 4 x 2 warp grid -> m16 x n32
    const int gr = lane >> 2, kc = (lane & 3) * 2;
    float c[4][4];
#pragma unroll
    for (int nf = 0; nf < 4; nf++)
#pragma unroll
        for (int i = 0; i < 4; i++) c[nf][i] = 0.0f;

    const __half* Ab = A + (size_t)(wm * 16 + gr) * lda + kc;
    const __half* Wb = W + (size_t)(wn * 32 + gr) * ldw + kc;
#pragma unroll 4
    for (int k0 = 0; k0 < klen; k0 += 16) {
        unsigned a0 = *(const unsigned*)(Ab + k0);
        unsigned a1 = *(const unsigned*)(Ab + 8 * lda + k0);
        unsigned a2 = *(const unsigned*)(Ab + k0 + 8);
        unsigned a3 = *(const unsigned*)(Ab + 8 * lda + k0 + 8);
#pragma unroll
        for (int nf = 0; nf < 4; nf++) {
            const __half* Br = Wb + (size_t)(nf * 8) * ldw + k0;
            unsigned b0 = *(const unsigned*)(Br);
            unsigned b1 = *(const unsigned*)(Br + 8);
            mma16816(c[nf], a0, a1, a2, a3, b0, b1);
        }
    }
    const int row = wm * 16 + gr;
#pragma unroll
    for (int nf = 0; nf < 4; nf++) {
        int col = wn * 32 + nf * 8 + kc;
        float add0 = 0.0f, add1 = 0.0f;
        if (bias) { add0 = bias[col]; add1 = bias[col + 1]; }
        float v0 = c[nf][0] + add0, v1 = c[nf][1] + add1;
        float v2 = c[nf][2] + add0, v3 = c[nf][3] + add1;
        if (dsth) {
            *(__half2*)(dsth + (size_t)row * dstr + col) = __floats2half2_rn(v0, v1);
            *(__half2*)(dsth + (size_t)(row + 8) * dstr + col) = __floats2half2_rn(v2, v3);
        } else {
            *(float2*)(dst + (size_t)row * dstr + col) = make_float2(v0, v1);
            *(float2*)(dst + (size_t)(row + 8) * dstr + col) = make_float2(v2, v3);
        }
    }
}

// ---------------- B1: e-scores for (batch b, t-chunk tc of 64) ----------------
__device__ __noinline__ void escore(int b, int tc, const float* __restrict__ w_score,
                                    SmemA& a) {
    const int tid = threadIdx.x;
    __syncthreads();
    for (int h = tid; h < HH; h += NTHR) {
        float sacc = 0.0f;
#pragma unroll
        for (int sl = 0; sl < 8; sl++)
            sacc += g_pdp[(size_t)(sl * 64 + b) * HH + h];
        a.pds[h] = sacc;
        a.wss[h] = w_score[h];
    }
    __syncthreads();
    const int warp = tid >> 5, lane = tid & 31;
    float pd16[16], ws16[16];
    {
        const float4* ps = (const float4*)a.pds;
        const float4* wsv = (const float4*)a.wss;
#pragma unroll
        for (int jj = 0; jj < 2; jj++) {
            int base = (lane + 32 * jj) * 2;
            float4 p0 = ps[base], p1 = ps[base + 1];
            float4 w0 = wsv[base], w1 = wsv[base + 1];
            pd16[jj * 8 + 0] = p0.x; pd16[jj * 8 + 1] = p0.y;
            pd16[jj * 8 + 2] = p0.z; pd16[jj * 8 + 3] = p0.w;
            pd16[jj * 8 + 4] = p1.x; pd16[jj * 8 + 5] = p1.y;
            pd16[jj * 8 + 6] = p1.z; pd16[jj * 8 + 7] = p1.w;
            ws16[jj * 8 + 0] = w0.x; ws16[jj * 8 + 1] = w0.y;
            ws16[jj * 8 + 2] = w0.z; ws16[jj * 8 + 3] = w0.w;
            ws16[jj * 8 + 4] = w1.x; ws16[jj * 8 + 5] = w1.y;
            ws16[jj * 8 + 6] = w1.z; ws16[jj * 8 + 7] = w1.w;
        }
    }
#pragma unroll
    for (int it = 0; it < 8; it++) {
        int t = tc * 64 + warp * 8 + it;
        const uint4* row = (const uint4*)(g_peh + ((size_t)b * TE + t) * HH);
        float acc = 0.0f;
#pragma unroll
        for (int jj = 0; jj < 2; jj++) {
            uint4 v = row[lane + 32 * jj];
            const float* pd = &pd16[jj * 8];
            const float* ws = &ws16[jj * 8];
            float2 f;
            f = __half22float2(*(__half2*)&v.x);
            acc += ws[0] * fast_tanh(pd[0] + f.x) + ws[1] * fast_tanh(pd[1] + f.y);
            f = __half22float2(*(__half2*)&v.y);
            acc += ws[2] * fast_tanh(pd[2] + f.x) + ws[3] * fast_tanh(pd[3] + f.y);
            f = __half22float2(*(__half2*)&v.z);
            acc += ws[4] * fast_tanh(pd[4] + f.x) + ws[5] * fast_tanh(pd[5] + f.y);
            f = __half22float2(*(__half2*)&v.w);
            acc += ws[6] * fast_tanh(pd[6] + f.x) + ws[7] * fast_tanh(pd[7] + f.y);
        }
#pragma unroll
        for (int off = 16; off > 0; off >>= 1)
            acc += __shfl_down_sync(0xffffffffu, acc, off);
        if (lane == 0) g_e[b * TE + t] = acc;
    }
}

// ---------------- B2: softmax + x_hat (ctx part via H2 + xx fold + bias) --------
// job (b, half): computes xhat[b, half*128 .. half*128+127] -> fp16
__device__ __noinline__ void xhat_job(int b, int half, const float* __restrict__ b_yattn,
                                      SmemA& a) {
    const int tid = threadIdx.x;
    __syncthreads();
    float ev = g_e[b * TE + tid];
    a.red[tid] = ev;
    __syncthreads();
    for (int s = 128; s > 0; s >>= 1) {
        if (tid < s) a.red[tid] = fmaxf(a.red[tid], a.red[tid + s]);
        __syncthreads();
    }
    float mx = a.red[0];
    __syncthreads();
    float p = __expf(ev - mx);
    a.red[tid] = p;
    __syncthreads();
    for (int s = 128; s > 0; s >>= 1) {
        if (tid < s) a.red[tid] += a.red[tid + s];
        __syncthreads();
    }
    float inv = 1.0f / a.red[0];
    a.ss[tid] = p * inv;
    __syncthreads();
    const int ml = tid & 127, th = tid >> 7;
    const int m = half * 128 + ml;
    const float* hb = g_h2 + ((size_t)b * TE + th * 128) * CIN + m;
    const float* ssp = &a.ss[th * 128];
    float a0 = 0, a1 = 0, a2 = 0, a3 = 0;
#pragma unroll 4
    for (int t = 0; t < 128; t += 4) {
        a0 += ssp[t + 0] * hb[(size_t)(t + 0) * CIN];
        a1 += ssp[t + 1] * hb[(size_t)(t + 1) * CIN];
        a2 += ssp[t + 2] * hb[(size_t)(t + 2) * CIN];
        a3 += ssp[t + 3] * hb[(size_t)(t + 3) * CIN];
    }
    __syncthreads();
    a.red[tid] = (a0 + a1) + (a2 + a3);
    __syncthreads();
    if (th == 0) {
        float v = a.red[tid] + a.red[tid + 128] + g_xp[b * CIN + m] + b_yattn[m];
        g_xhath[b * CIN + m] = __float2half_rn(v);
    }
}

// ---------------- epilogue: softmax + ctx quarter (from last-step g_e) ---------
__device__ __noinline__ void ctx_job(int b, int qm, SmemA& a) {
    const int tid = threadIdx.x;
    __syncthreads();
    float ev = g_e[b * TE + tid];
    a.red[tid] = ev;
    __syncthreads();
    for (int s = 128; s > 0; s >>= 1) {
        if (tid < s) a.red[tid] = fmaxf(a.red[tid], a.red[tid + s]);
        __syncthreads();
    }
    float mx = a.red[0];
    __syncthreads();
    float p = __expf(ev - mx);
    a.red[tid] = p;
    __syncthreads();
    for (int s = 128; s > 0; s >>= 1) {
        if (tid < s) a.red[tid] += a.red[tid + s];
        __syncthreads();
    }
    float inv = 1.0f / a.red[0];
    a.ss[tid] = p * inv;
    __syncthreads();
    const int ml = tid & 127, th = tid >> 7;
    const int m = qm * 128 + ml;
    const __half* hb = g_henh + ((size_t)b * TE + th * 128) * HH + m;
    const float* ssp = &a.ss[th * 128];
    float a0 = 0, a1 = 0;
#pragma unroll 4
    for (int t = 0; t < 128; t += 2) {
        a0 += ssp[t + 0] * __half2float(hb[(size_t)(t + 0) * HH]);
        a1 += ssp[t + 1] * __half2float(hb[(size_t)(t + 1) * HH]);
    }
    __syncthreads();
    a.red[tid] = a0 + a1;
    __syncthreads();
    if (th == 0)
        g_ctxh[b * HH + m] = __float2half_rn(a.red[tid] + a.red[tid + 128]);
}

// ---------------- prologue pack kernel ----------------
__global__ void k_pack(const float* __restrict__ x, const float* __restrict__ h_en,
                       const float* __restrict__ W_dec, const float* __restrict__ W_enc,
                       const float* __restrict__ W_yattn,
                       const float* __restrict__ W_ih, const float* __restrict__ W_hh,
                       const float* __restrict__ W_ff1, const float* __restrict__ W_ff2,
                       const float* __restrict__ W_ta, const float* __restrict__ W_tb,
                       const float* __restrict__ b_ff1, const float* __restrict__ b_ff2,
                       const float* __restrict__ b_ta, const float* __restrict__ b_tb,
                       const float* __restrict__ W_o1, const float* __restrict__ W_o2) {
    if (blockIdx.x == 0 && threadIdx.x == 0) g_arr = 0ull;
    const int N1 = G4 * CAT;
    const int N2 = 3 * HH * CAT;
    const int N3 = 3 * HH;
    const int N4 = HH * 1024;
    const int N5 = CIN * CAT;
    const int N6 = HH * 1024;
    const int N7 = OUTN * HH;
    const int N8 = HH * HH;
    const int N9 = BB * LL * CIN;
    const int N10 = BB * TE * HH;
    const int T1 = N1, T2 = T1 + N2, T3 = T2 + N3, T4 = T3 + N4, T5 = T4 + N5;
    const int T6 = T5 + N6, T7 = T6 + N7, T8 = T7 + N8, T9 = T8 + N9;
    const int total = T9 + N10;
    for (int i = blockIdx.x * blockDim.x + threadIdx.x; i < total;
         i += gridDim.x * blockDim.x) {
        if (i < T1) {
            int nn = i / CAT, k = i % CAT;
            float v = (k < CIN) ? W_ih[nn * CIN + k] : W_hh[nn * HH + (k - CIN)];
            g_w6h[i] = __float2half_rn(v);
        } else if (i < T2) {
            int j = i - T1;
            int nn = j / CAT, k = j % CAT;
            int gate = nn / HH, u = nn % HH;
            float v;
            if (gate == 0)      v = W_ff1[u * CAT + k];
            else if (gate == 1) v = W_ff2[u * CAT + k];
            else                v = W_ta[u * CAT + k] + W_tb[u * CAT + k];
            g_w3h[j] = __float2half_rn(v);
        } else if (i < T3) {
            int nn = i - T2;
            int gate = nn / HH, u = nn % HH;
            g_b3[nn] = (gate == 0) ? b_ff1[u] : (gate == 1) ? b_ff2[u]
                                              : (b_ta[u] + b_tb[u]);
        } else if (i < T4) {
            int j = i - T3;
            g_wdh[j] = __float2half_rn(W_dec[j]);
        } else if (i < T5) {
            int j = i - T4;
            g_wyh[j] = __float2half_rn(W_yattn[j]);
        } else if (i < T6) {
            int j = i - T5;
            g_wo1h[j] = __float2half_rn(W_o1[j]);
        } else if (i < T7) {
            int j = i - T6;
            g_wo2h[j] = __float2half_rn(W_o2[j]);
        } else if (i < T8) {
            int j = i - T7;
            g_wench[j] = __float2half_rn(W_enc[j]);
        } else if (i < T9) {
            int j = i - T8;
            g_xh[j] = __float2half_rn(x[j]);
        } else {
            int j = i - T9;
            g_henh[j] = __float2half_rn(h_en[j]);
        }
    }
}

// ---------------- the persistent uber-kernel ----------------
__global__ void __launch_bounds__(NTHR, 2)
k_main(const float* __restrict__ b_enc, const float* __restrict__ w_score,
       const float* __restrict__ b_yattn, const float* __restrict__ b_ih,
       const float* __restrict__ b_o1, const float* __restrict__ b_o2,
       float* __restrict__ out, int write_state) {
    __shared__ SmemA sa;
    const int bid = blockIdx.x;
    const int tid = threadIdx.x;
    const int gstep = NBLK * NTHR;
    unsigned long long bar_t = 0;

    // ---- P0: init states + proj_enc -> fp16 + H2 -> fp32 ----
    for (int idx = bid * NTHR + tid; idx < BB * HH; idx += gstep) {
        g_h[idx] = 0.0f; g_c[idx] = 0.0f;
        g_hh[idx] = __float2half_rn(0.0f);
        g_ch[idx] = __float2half_rn(0.0f);
    }
    for (int j = bid; j < 3072; j += NBLK) {
        if (j < 2048) {
            int mt = j >> 3, nt = j & 7;
            gemm_mma(g_henh + (size_t)mt * 64 * HH, HH,
                     g_wench + (size_t)(nt * 64) * HH, HH, HH,
                     nullptr, HH, g_peh + (size_t)mt * 64 * HH + nt * 64,
                     b_enc + nt * 64);
        } else {
            int q = j - 2048;               // H2: 256 mt x 4 nt
            int mt = q >> 2, nt = q & 3;
            gemm_mma(g_henh + (size_t)mt * 64 * HH, HH,
                     g_wyh + (size_t)(nt * 64) * CAT + CIN, CAT, HH,
                     g_h2 + (size_t)mt * 64 * CIN + nt * 64, CIN, nullptr, nullptr);
        }
    }
    GSYNC();

    for (int t = 0; t < LL; t++) {
        // ---- A: pd (8nt x 8ks k128 = 64) + zh (32nt x 4ks k128 = 128) + xx (4, k256)
        for (int j = bid; j < 196; j += NBLK) {
            if (j < 64) {
                int nt = j >> 3, ks = j & 7;
                const __half* A = (ks < 4) ? g_hh + ks * 128 : g_ch + (ks - 4) * 128;
                gemm_mma(A, HH, g_wdh + (size_t)(nt * 64) * 1024 + ks * 128, 1024, 128,
                         g_pdp + (size_t)ks * 64 * HH + nt * 64, HH, nullptr, nullptr);
            } else if (j < 192) {
                int q = j - 64;
                int nt = q >> 2, ks = q & 3;
                gemm_mma(g_hh + ks * 128, HH,
                         g_w6h + (size_t)(nt * 64) * CAT + CIN + ks * 128, CAT, 128,
                         g_zp + (size_t)ks * 64 * G4 + nt * 64, G4, nullptr, nullptr);
            } else {
                int nt = j - 192;
                gemm_mma(g_xh + (size_t)t * CIN, LL * CIN,
                         g_wyh + (size_t)(nt * 64) * CAT, CAT, 256,
                         g_xp + nt * 64, CIN, nullptr, nullptr);
            }
        }
        GSYNC();
        // ---- B1: e-scores (64 b x 4 tc = 256 jobs) ----
        for (int j = bid; j < 256; j += NBLK) {
            escore(j >> 2, j & 3, w_score, sa);
        }
        GSYNC();
        // ---- B2: softmax + x_hat halves (128 jobs) ----
        for (int j = bid; j < 128; j += NBLK) {
            xhat_job(j >> 1, j & 1, b_yattn, sa);
        }
        GSYNC();
        // ---- D: zx (32nt x 2ks = 64, zp 4-5) + cfcx (24nt x 2ks = 48, fp 4-5) ----
        for (int j = bid; j < 112; j += NBLK) {
            if (j < 64) {
                int nt = j >> 1, ks = j & 1;
                gemm_mma(g_xhath + ks * 128, CIN,
                         g_w6h + (size_t)(nt * 64) * CAT + ks * 128, CAT, 128,
                         g_zp + (size_t)(4 + ks) * 64 * G4 + nt * 64, G4, nullptr, nullptr);
            } else {
                int q = j - 64;
                int nt = q >> 1, ks = q & 1;
                gemm_mma(g_xhath + ks * 128, CIN,
                         g_w3h + (size_t)(nt * 64) * CAT + ks * 128, CAT, 128,
                         g_fp + (size_t)(4 + ks) * 64 * (3 * HH) + nt * 64, 3 * HH,
                         nullptr, nullptr);
            }
        }
        GSYNC();
        // ---- E: LSTM pointwise (fold zp 0-5) ----
        for (int idx = bid * NTHR + tid; idx < BB * HH; idx += gstep) {
            int m = idx >> 9, u = idx & 511;
            float zi = b_ih[u], zg = b_ih[u + 512], zf = b_ih[u + 1024], zo = b_ih[u + 1536];
#pragma unroll
            for (int sl = 0; sl < 6; sl++) {
                const float* p = g_zp + (size_t)(sl * 64 + m) * G4;
                zi += p[u]; zg += p[u + 512]; zf += p[u + 1024]; zo += p[u + 1536];
            }
            float c_old = g_c[idx];
            float nc = c_old * sigm(zf + 1.0f) + tanhf(zi) * sigm(zg);
            g_c[idx] = nc;
            g_ch[idx] = __float2half_rn(nc);
            float hl = tanhf(nc) * sigm(zo);
            g_hlh[idx] = __float2half_rn(hl);
        }
        GSYNC();
        // ---- F: cfc h-part (24nt x 4ks k128 = 96, fp 0-3) ----
        for (int j = bid; j < 96; j += NBLK) {
            int nt = j >> 2, ks = j & 3;
            gemm_mma(g_hlh + ks * 128, HH,
                     g_w3h + (size_t)(nt * 64) * CAT + CIN + ks * 128, CAT, 128,
                     g_fp + (size_t)ks * 64 * (3 * HH) + nt * 64, 3 * HH, nullptr, nullptr);
        }
        GSYNC();
        // ---- G: CfC pointwise (fold fp 0-5) -> new h ----
        for (int idx = bid * NTHR + tid; idx < BB * HH; idx += gstep) {
            int m = idx >> 9, u = idx & 511;
            float f1 = g_b3[u], f2 = g_b3[u + 512], tg = g_b3[u + 1024];
#pragma unroll
            for (int sl = 0; sl < 6; sl++) {
                const float* p = g_fp + (size_t)(sl * 64 + m) * (3 * HH);
                f1 += p[u]; f2 += p[u + 512]; tg += p[u + 1024];
            }
            float ti = sigm(tg);
            float nh = tanhf(f1) * (1.0f - ti) + ti * tanhf(f2);
            g_h[idx] = nh;
            g_hh[idx] = __float2half_rn(nh);
        }
        GSYNC();
    }

    // ---- EP0: ctx from last-step scores (64 b x 4 quarters = 256 jobs) ----
    for (int j = bid; j < 256; j += NBLK) {
        ctx_job(j >> 2, j & 3, sa);
    }
    GSYNC();
    // ---- EP1: O1 GEMM ([h|ctx], K=1024): 8nt x 8ks k128 = 64 jobs -> zp ----
    for (int j = bid; j < 64; j += NBLK) {
        int nt = j >> 3, ks = j & 7;
        const __half* A = (ks < 4) ? g_hh + ks * 128 : g_ctxh + (ks - 4) * 128;
        gemm_mma(A, HH, g_wo1h + (size_t)(nt * 64) * 1024 + ks * 128, 1024, 128,
                 g_zp + (size_t)ks * 64 * HH + nt * 64, HH, nullptr, nullptr);
    }
    GSYNC();
    // ---- EP2: reduce 8 + leaky relu -> fp16 hid ----
    for (int idx = bid * NTHR + tid; idx < BB * HH; idx += gstep) {
        int m = idx >> 9, u = idx & 511;
        float s = b_o1[u];
#pragma unroll
        for (int sl = 0; sl < 8; sl++)
            s += g_zp[(size_t)(sl * 64 + m) * HH + u];
        g_hidh[idx] = __float2half_rn((s > 0.0f) ? s : 0.01f * s);
    }
    GSYNC();
    // ---- EP3: O2 GEMM (hid, K=512): 2nt x 4ks k128 = 8 jobs -> fp ----
    for (int j = bid; j < 8; j += NBLK) {
        int nt = j >> 2, ks = j & 3;
        gemm_mma(g_hidh + ks * 128, HH,
                 g_wo2h + (size_t)(nt * 64) * HH + ks * 128, HH, 128,
                 g_fp + (size_t)ks * 64 * OUTN + nt * 64, OUTN, nullptr, nullptr);
    }
    GSYNC();
    // ---- EP4: final reduce + bias (+ optional state copy) ----
    for (int idx = bid * NTHR + tid; idx < BB * OUTN; idx += gstep) {
        int m = idx >> 7, u = idx & 127;
        float s = b_o2[u];
#pragma unroll
        for (int sl = 0; sl < 4; sl++)
            s += g_fp[(size_t)(sl * 64 + m) * OUTN + u];
        out[idx] = s;
    }
    if (write_state) {
        for (int idx = bid * NTHR + tid; idx < BB * HH; idx += gstep) {
            out[BB * OUTN + idx] = g_h[idx];
            out[BB * OUTN + BB * HH + idx] = g_c[idx];
        }
    }
}

// ============================================================================
extern "C" void kernel_launch(void* const* d_in, const int* in_sizes, int n_in,
                              void* d_out, int out_size) {
    const float* x       = (const float*)d_in[0];
    const float* h_en    = (const float*)d_in[1];
    const float* W_dec   = (const float*)d_in[2];
    const float* W_enc   = (const float*)d_in[3];
    const float* b_enc   = (const float*)d_in[4];
    const float* w_score = (const float*)d_in[5];
    const float* W_yattn = (const float*)d_in[6];
    const float* b_yattn = (const float*)d_in[7];
    const float* W_ih    = (const float*)d_in[8];
    const float* b_ih    = (const float*)d_in[9];
    const float* W_hh    = (const float*)d_in[10];
    const float* W_ff1   = (const float*)d_in[11];
    const float* b_ff1   = (const float*)d_in[12];
    const float* W_ff2   = (const float*)d_in[13];
    const float* b_ff2   = (const float*)d_in[14];
    const float* W_ta    = (const float*)d_in[15];
    const float* b_ta    = (const float*)d_in[16];
    const float* W_tb    = (const float*)d_in[17];
    const float* b_tb    = (const float*)d_in[18];
    const float* W_o1    = (const float*)d_in[19];
    const float* b_o1    = (const float*)d_in[20];
    const float* W_o2    = (const float*)d_in[21];
    const float* b_o2    = (const float*)d_in[22];
    float* out = (float*)d_out;

    int write_state = (out_size >= BB * OUTN + 2 * BB * HH) ? 1 : 0;

    k_pack<<<512, 256>>>(x, h_en, W_dec, W_enc, W_yattn, W_ih, W_hh,
                         W_ff1, W_ff2, W_ta, W_tb,
                         b_ff1, b_ff2, b_ta, b_tb, W_o1, W_o2);
    k_main<<<NBLK, NTHR>>>(b_enc, w_score, b_yattn, b_ih,
                           b_o1, b_o2, out, write_state);
}

// round 13
// speedup vs baseline: 3.4847x; 1.4842x over previous
#include <cuda_runtime.h>
#include <cuda_fp16.h>
#include <cstdint>

#define BB   64
#define LL   128
#define TE   256
#define CIN  256
#define HH   512
#define CAT  768
#define G4   2048
#define OUTN 128
#define NBLK 288
#define NTHR 256

// ---------------- persistent device buffers ----------------
__device__ __half g_peh[(size_t)BB * TE * HH];   // proj_enc fp16 (16 MB)
__device__ __half g_henh[(size_t)BB * TE * HH];  // h_en fp16 (16 MB)
__device__ __half g_xh[(size_t)BB * LL * CIN];   // x fp16 (4 MB)
__device__ float g_h2[(size_t)BB * TE * CIN];    // h_en @ Wy_ctx^T (16 MB fp32)
__device__ float g_e[BB * TE];
__device__ float g_pdp[8 * 64 * HH];             // pd partials (8 slices k128)
__device__ float g_xp[64 * CIN];                 // xx partial (1 slice K=256)
__device__ float g_zp[6 * 64 * G4];              // z partials (zh:0-3, zx:4-5; epi O1)
__device__ float g_fp[6 * 64 * 3 * HH];          // cfc partials (h:0-3, x:4-5; epi O2)
__device__ float g_h[BB * HH];
__device__ float g_c[BB * HH];
// fp16 activation twins (GEMM A operands)
__device__ __half g_hh[BB * HH];
__device__ __half g_ch[BB * HH];
__device__ __half g_ctxh[BB * HH];
__device__ __half g_xhath[BB * CIN];
__device__ __half g_hlh[BB * HH];
__device__ __half g_hidh[BB * HH];
// fp16 weights
__device__ __half g_w6h[G4 * CAT];               // [W_ih | W_hh]
__device__ __half g_w3h[3 * HH * CAT];           // [ff1; ff2; ta+tb]
__device__ __half g_wdh[HH * 1024];              // W_dec
__device__ __half g_wyh[CIN * CAT];              // W_yattn
__device__ __half g_wo1h[HH * 1024];             // W_o1
__device__ __half g_wo2h[OUTN * HH];             // W_o2
__device__ __half g_wench[HH * HH];              // W_enc
__device__ float g_b3[3 * HH];
__device__ unsigned long long g_arr;             // monotonic barrier counter

// ---------------- helpers ----------------
__device__ __forceinline__ float fast_tanh(float x) {
    float y;
    asm("tanh.approx.f32 %0, %1;" : "=f"(y) : "f"(x));
    return y;
}
__device__ __forceinline__ float sigm(float x) {
    return 1.0f / (1.0f + __expf(-x));
}
__device__ __forceinline__ void cpa16(void* smem, const void* gmem) {
    unsigned s = (unsigned)__cvta_generic_to_shared(smem);
    asm volatile("cp.async.ca.shared.global [%0], [%1], 16;" :: "r"(s), "l"(gmem));
}

// ---------------- fast global barrier (monotonic counter) ----------------
#define GSYNC() do {                                                     \
    __syncthreads();                                                     \
    if (threadIdx.x == 0) {                                              \
        __threadfence();                                                 \
        bar_t += NBLK;                                                   \
        atomicAdd(&g_arr, 1ull);                                         \
        while (*(volatile unsigned long long*)&g_arr < bar_t) { }        \
        __threadfence();                                                 \
    }                                                                    \
    __syncthreads();                                                     \
} while (0)

// ---------------- shared memory ----------------
struct SmemG { __half A[64][136]; __half W[64][136]; };   // 34.8 KB
struct SmemA { float pds[HH]; float wss[HH]; float ss[TE]; float red[NTHR]; };
union Smem { SmemG g; SmemA a; };

// ---------------- mma.sync m16n8k16 fp16 -> fp32 ----------------
__device__ __forceinline__ void mma16816(float* c, unsigned a0, unsigned a1,
                                         unsigned a2, unsigned a3,
                                         unsigned b0, unsigned b1) {
    asm volatile(
        "mma.sync.aligned.m16n8k16.row.col.f32.f16.f16.f32 "
        "{%0,%1,%2,%3}, {%4,%5,%6,%7}, {%8,%9}, {%0,%1,%2,%3};"
        : "+f"(c[0]), "+f"(c[1]), "+f"(c[2]), "+f"(c[3])
        : "r"(a0), "r"(a1), "r"(a2), "r"(a3), "r"(b0), "r"(b1));
}

// ---------------- 64x64xK GEMM job, 256 threads, cp.async smem staging ---------
// A fp16 row-major (64 x klen, ld lda), W fp16 row-major (64 x klen, ld ldw;
// W rows = output cols). klen % 128 == 0. All base pointers 16B-aligned,
// lda/ldw multiples of 8.
__device__ __noinline__ void gemm_mma(const __half* __restrict__ A, int lda,
                                      const __half* __restrict__ W, int ldw,
                                      int klen,
                                      float* __restrict__ dst, int dstr,
                                      __half* __restrict__ dsth,
                                      const float* __restrict__ bias, SmemG& s) {
    const int tid  = threadIdx.x;
    const int lane = tid & 31, wid = tid >> 5;
    const int wm = wid >> 1, wn = wid & 1;      // 4 x 2 warp grid -> m16 x n32
    const int gr = lane >> 2, kc = (lane & 3) * 2;
    const int lr = tid >> 2;                    // staging row 0..63
    const int lu = tid & 3;                     // staging unit group
    float c[4][4];
#pragma unroll
    for (int nf = 0; nf < 4; nf++)
#pragma unroll
        for (int i = 0; i < 4; i++) c[nf][i] = 0.0f;

    for (int kb = 0; kb < klen; kb += 128) {
        __syncthreads();   // previous chunk's smem reads complete
        const __half* Ar = A + (size_t)lr * lda + kb;
        const __half* Wr = W + (size_t)lr * ldw + kb;
#pragma unroll
        for (int u = 0; u < 4; u++) {
            int unit = lu + 4 * u;              // 0..15 (16B units of the 256B row)
            cpa16(&s.A[lr][unit * 8], Ar + unit * 8);
            cpa16(&s.W[lr][unit * 8], Wr + unit * 8);
        }
        asm volatile("cp.async.commit_group;");
        asm volatile("cp.async.wait_group 0;" ::: "memory");
        __syncthreads();
#pragma unroll
        for (int k0 = 0; k0 < 128; k0 += 16) {
            unsigned a0 = *(const unsigned*)&s.A[wm * 16 + gr][k0 + kc];
            unsigned a1 = *(const unsigned*)&s.A[wm * 16 + gr + 8][k0 + kc];
            unsigned a2 = *(const unsigned*)&s.A[wm * 16 + gr][k0 + kc + 8];
            unsigned a3 = *(const unsigned*)&s.A[wm * 16 + gr + 8][k0 + kc + 8];
#pragma unroll
            for (int nf = 0; nf < 4; nf++) {
                unsigned b0 = *(const unsigned*)&s.W[wn * 32 + nf * 8 + gr][k0 + kc];
                unsigned b1 = *(const unsigned*)&s.W[wn * 32 + nf * 8 + gr][k0 + kc + 8];
                mma16816(c[nf], a0, a1, a2, a3, b0, b1);
            }
        }
    }
    const int row = wm * 16 + gr;
#pragma unroll
    for (int nf = 0; nf < 4; nf++) {
        int col = wn * 32 + nf * 8 + kc;
        float add0 = 0.0f, add1 = 0.0f;
        if (bias) { add0 = bias[col]; add1 = bias[col + 1]; }
        float v0 = c[nf][0] + add0, v1 = c[nf][1] + add1;
        float v2 = c[nf][2] + add0, v3 = c[nf][3] + add1;
        if (dsth) {
            *(__half2*)(dsth + (size_t)row * dstr + col) = __floats2half2_rn(v0, v1);
            *(__half2*)(dsth + (size_t)(row + 8) * dstr + col) = __floats2half2_rn(v2, v3);
        } else {
            *(float2*)(dst + (size_t)row * dstr + col) = make_float2(v0, v1);
            *(float2*)(dst + (size_t)(row + 8) * dstr + col) = make_float2(v2, v3);
        }
    }
}

// ---------------- B1: e-scores for (batch b, t-chunk tc of 64) ----------------
__device__ __noinline__ void escore(int b, int tc, const float* __restrict__ w_score,
                                    SmemA& a) {
    const int tid = threadIdx.x;
    __syncthreads();
    for (int h = tid; h < HH; h += NTHR) {
        float sacc = 0.0f;
#pragma unroll
        for (int sl = 0; sl < 8; sl++)
            sacc += g_pdp[(size_t)(sl * 64 + b) * HH + h];
        a.pds[h] = sacc;
        a.wss[h] = w_score[h];
    }
    __syncthreads();
    const int warp = tid >> 5, lane = tid & 31;
    float pd16[16], ws16[16];
    {
        const float4* ps = (const float4*)a.pds;
        const float4* wsv = (const float4*)a.wss;
#pragma unroll
        for (int jj = 0; jj < 2; jj++) {
            int base = (lane + 32 * jj) * 2;
            float4 p0 = ps[base], p1 = ps[base + 1];
            float4 w0 = wsv[base], w1 = wsv[base + 1];
            pd16[jj * 8 + 0] = p0.x; pd16[jj * 8 + 1] = p0.y;
            pd16[jj * 8 + 2] = p0.z; pd16[jj * 8 + 3] = p0.w;
            pd16[jj * 8 + 4] = p1.x; pd16[jj * 8 + 5] = p1.y;
            pd16[jj * 8 + 6] = p1.z; pd16[jj * 8 + 7] = p1.w;
            ws16[jj * 8 + 0] = w0.x; ws16[jj * 8 + 1] = w0.y;
            ws16[jj * 8 + 2] = w0.z; ws16[jj * 8 + 3] = w0.w;
            ws16[jj * 8 + 4] = w1.x; ws16[jj * 8 + 5] = w1.y;
            ws16[jj * 8 + 6] = w1.z; ws16[jj * 8 + 7] = w1.w;
        }
    }
#pragma unroll
    for (int it = 0; it < 8; it++) {
        int t = tc * 64 + warp * 8 + it;
        const uint4* row = (const uint4*)(g_peh + ((size_t)b * TE + t) * HH);
        float acc = 0.0f;
#pragma unroll
        for (int jj = 0; jj < 2; jj++) {
            uint4 v = row[lane + 32 * jj];
            const float* pd = &pd16[jj * 8];
            const float* ws = &ws16[jj * 8];
            float2 f;
            f = __half22float2(*(__half2*)&v.x);
            acc += ws[0] * fast_tanh(pd[0] + f.x) + ws[1] * fast_tanh(pd[1] + f.y);
            f = __half22float2(*(__half2*)&v.y);
            acc += ws[2] * fast_tanh(pd[2] + f.x) + ws[3] * fast_tanh(pd[3] + f.y);
            f = __half22float2(*(__half2*)&v.z);
            acc += ws[4] * fast_tanh(pd[4] + f.x) + ws[5] * fast_tanh(pd[5] + f.y);
            f = __half22float2(*(__half2*)&v.w);
            acc += ws[6] * fast_tanh(pd[6] + f.x) + ws[7] * fast_tanh(pd[7] + f.y);
        }
#pragma unroll
        for (int off = 16; off > 0; off >>= 1)
            acc += __shfl_down_sync(0xffffffffu, acc, off);
        if (lane == 0) g_e[b * TE + t] = acc;
    }
}

// ---------------- B2: softmax + x_hat (ctx part via H2 + xx fold + bias) --------
__device__ __noinline__ void xhat_job(int b, int half, const float* __restrict__ b_yattn,
                                      SmemA& a) {
    const int tid = threadIdx.x;
    __syncthreads();
    float ev = g_e[b * TE + tid];
    a.red[tid] = ev;
    __syncthreads();
    for (int s = 128; s > 0; s >>= 1) {
        if (tid < s) a.red[tid] = fmaxf(a.red[tid], a.red[tid + s]);
        __syncthreads();
    }
    float mx = a.red[0];
    __syncthreads();
    float p = __expf(ev - mx);
    a.red[tid] = p;
    __syncthreads();
    for (int s = 128; s > 0; s >>= 1) {
        if (tid < s) a.red[tid] += a.red[tid + s];
        __syncthreads();
    }
    float inv = 1.0f / a.red[0];
    a.ss[tid] = p * inv;
    __syncthreads();
    const int ml = tid & 127, th = tid >> 7;
    const int m = half * 128 + ml;
    const float* hb = g_h2 + ((size_t)b * TE + th * 128) * CIN + m;
    const float* ssp = &a.ss[th * 128];
    float a0 = 0, a1 = 0, a2 = 0, a3 = 0;
#pragma unroll 4
    for (int t = 0; t < 128; t += 4) {
        a0 += ssp[t + 0] * hb[(size_t)(t + 0) * CIN];
        a1 += ssp[t + 1] * hb[(size_t)(t + 1) * CIN];
        a2 += ssp[t + 2] * hb[(size_t)(t + 2) * CIN];
        a3 += ssp[t + 3] * hb[(size_t)(t + 3) * CIN];
    }
    __syncthreads();
    a.red[tid] = (a0 + a1) + (a2 + a3);
    __syncthreads();
    if (th == 0) {
        float v = a.red[tid] + a.red[tid + 128] + g_xp[b * CIN + m] + b_yattn[m];
        g_xhath[b * CIN + m] = __float2half_rn(v);
    }
}

// ---------------- epilogue: softmax + ctx quarter (from last-step g_e) ---------
__device__ __noinline__ void ctx_job(int b, int qm, SmemA& a) {
    const int tid = threadIdx.x;
    __syncthreads();
    float ev = g_e[b * TE + tid];
    a.red[tid] = ev;
    __syncthreads();
    for (int s = 128; s > 0; s >>= 1) {
        if (tid < s) a.red[tid] = fmaxf(a.red[tid], a.red[tid + s]);
        __syncthreads();
    }
    float mx = a.red[0];
    __syncthreads();
    float p = __expf(ev - mx);
    a.red[tid] = p;
    __syncthreads();
    for (int s = 128; s > 0; s >>= 1) {
        if (tid < s) a.red[tid] += a.red[tid + s];
        __syncthreads();
    }
    float inv = 1.0f / a.red[0];
    a.ss[tid] = p * inv;
    __syncthreads();
    const int ml = tid & 127, th = tid >> 7;
    const int m = qm * 128 + ml;
    const __half* hb = g_henh + ((size_t)b * TE + th * 128) * HH + m;
    const float* ssp = &a.ss[th * 128];
    float a0 = 0, a1 = 0;
#pragma unroll 4
    for (int t = 0; t < 128; t += 2) {
        a0 += ssp[t + 0] * __half2float(hb[(size_t)(t + 0) * HH]);
        a1 += ssp[t + 1] * __half2float(hb[(size_t)(t + 1) * HH]);
    }
    __syncthreads();
    a.red[tid] = a0 + a1;
    __syncthreads();
    if (th == 0)
        g_ctxh[b * HH + m] = __float2half_rn(a.red[tid] + a.red[tid + 128]);
}

// ---------------- prologue pack kernel ----------------
__global__ void k_pack(const float* __restrict__ x, const float* __restrict__ h_en,
                       const float* __restrict__ W_dec, const float* __restrict__ W_enc,
                       const float* __restrict__ W_yattn,
                       const float* __restrict__ W_ih, const float* __restrict__ W_hh,
                       const float* __restrict__ W_ff1, const float* __restrict__ W_ff2,
                       const float* __restrict__ W_ta, const float* __restrict__ W_tb,
                       const float* __restrict__ b_ff1, const float* __restrict__ b_ff2,
                       const float* __restrict__ b_ta, const float* __restrict__ b_tb,
                       const float* __restrict__ W_o1, const float* __restrict__ W_o2) {
    if (blockIdx.x == 0 && threadIdx.x == 0) g_arr = 0ull;
    const int N1 = G4 * CAT;
    const int N2 = 3 * HH * CAT;
    const int N3 = 3 * HH;
    const int N4 = HH * 1024;
    const int N5 = CIN * CAT;
    const int N6 = HH * 1024;
    const int N7 = OUTN * HH;
    const int N8 = HH * HH;
    const int N9 = BB * LL * CIN;
    const int N10 = BB * TE * HH;
    const int T1 = N1, T2 = T1 + N2, T3 = T2 + N3, T4 = T3 + N4, T5 = T4 + N5;
    const int T6 = T5 + N6, T7 = T6 + N7, T8 = T7 + N8, T9 = T8 + N9;
    const int total = T9 + N10;
    for (int i = blockIdx.x * blockDim.x + threadIdx.x; i < total;
         i += gridDim.x * blockDim.x) {
        if (i < T1) {
            int nn = i / CAT, k = i % CAT;
            float v = (k < CIN) ? W_ih[nn * CIN + k] : W_hh[nn * HH + (k - CIN)];
            g_w6h[i] = __float2half_rn(v);
        } else if (i < T2) {
            int j = i - T1;
            int nn = j / CAT, k = j % CAT;
            int gate = nn / HH, u = nn % HH;
            float v;
            if (gate == 0)      v = W_ff1[u * CAT + k];
            else if (gate == 1) v = W_ff2[u * CAT + k];
            else                v = W_ta[u * CAT + k] + W_tb[u * CAT + k];
            g_w3h[j] = __float2half_rn(v);
        } else if (i < T3) {
            int nn = i - T2;
            int gate = nn / HH, u = nn % HH;
            g_b3[nn] = (gate == 0) ? b_ff1[u] : (gate == 1) ? b_ff2[u]
                                              : (b_ta[u] + b_tb[u]);
        } else if (i < T4) {
            int j = i - T3;
            g_wdh[j] = __float2half_rn(W_dec[j]);
        } else if (i < T5) {
            int j = i - T4;
            g_wyh[j] = __float2half_rn(W_yattn[j]);
        } else if (i < T6) {
            int j = i - T5;
            g_wo1h[j] = __float2half_rn(W_o1[j]);
        } else if (i < T7) {
            int j = i - T6;
            g_wo2h[j] = __float2half_rn(W_o2[j]);
        } else if (i < T8) {
            int j = i - T7;
            g_wench[j] = __float2half_rn(W_enc[j]);
        } else if (i < T9) {
            int j = i - T8;
            g_xh[j] = __float2half_rn(x[j]);
        } else {
            int j = i - T9;
            g_henh[j] = __float2half_rn(h_en[j]);
        }
    }
}

// ---------------- the persistent uber-kernel ----------------
__global__ void __launch_bounds__(NTHR, 2)
k_main(const float* __restrict__ b_enc, const float* __restrict__ w_score,
       const float* __restrict__ b_yattn, const float* __restrict__ b_ih,
       const float* __restrict__ b_o1, const float* __restrict__ b_o2,
       float* __restrict__ out, int write_state) {
    __shared__ Smem sm;
    const int bid = blockIdx.x;
    const int tid = threadIdx.x;
    const int gstep = NBLK * NTHR;
    unsigned long long bar_t = 0;

    // ---- P0: init states + proj_enc -> fp16 + H2 -> fp32 ----
    for (int idx = bid * NTHR + tid; idx < BB * HH; idx += gstep) {
        g_h[idx] = 0.0f; g_c[idx] = 0.0f;
        g_hh[idx] = __float2half_rn(0.0f);
        g_ch[idx] = __float2half_rn(0.0f);
    }
    for (int j = bid; j < 3072; j += NBLK) {
        if (j < 2048) {
            int mt = j >> 3, nt = j & 7;
            gemm_mma(g_henh + (size_t)mt * 64 * HH, HH,
                     g_wench + (size_t)(nt * 64) * HH, HH, HH,
                     nullptr, HH, g_peh + (size_t)mt * 64 * HH + nt * 64,
                     b_enc + nt * 64, sm.g);
        } else {
            int q = j - 2048;               // H2: 256 mt x 4 nt
            int mt = q >> 2, nt = q & 3;
            gemm_mma(g_henh + (size_t)mt * 64 * HH, HH,
                     g_wyh + (size_t)(nt * 64) * CAT + CIN, CAT, HH,
                     g_h2 + (size_t)mt * 64 * CIN + nt * 64, CIN, nullptr, nullptr, sm.g);
        }
    }
    GSYNC();

    for (int t = 0; t < LL; t++) {
        // ---- A: pd (64) + zh (128) + xx (4, k256) = 196 jobs ----
        for (int j = bid; j < 196; j += NBLK) {
            if (j < 64) {
                int nt = j >> 3, ks = j & 7;
                const __half* A = (ks < 4) ? g_hh + ks * 128 : g_ch + (ks - 4) * 128;
                gemm_mma(A, HH, g_wdh + (size_t)(nt * 64) * 1024 + ks * 128, 1024, 128,
                         g_pdp + (size_t)ks * 64 * HH + nt * 64, HH, nullptr, nullptr, sm.g);
            } else if (j < 192) {
                int q = j - 64;
                int nt = q >> 2, ks = q & 3;
                gemm_mma(g_hh + ks * 128, HH,
                         g_w6h + (size_t)(nt * 64) * CAT + CIN + ks * 128, CAT, 128,
                         g_zp + (size_t)ks * 64 * G4 + nt * 64, G4, nullptr, nullptr, sm.g);
            } else {
                int nt = j - 192;
                gemm_mma(g_xh + (size_t)t * CIN, LL * CIN,
                         g_wyh + (size_t)(nt * 64) * CAT, CAT, 256,
                         g_xp + nt * 64, CIN, nullptr, nullptr, sm.g);
            }
        }
        GSYNC();
        // ---- B1: e-scores (64 b x 4 tc = 256 jobs) ----
        for (int j = bid; j < 256; j += NBLK) {
            escore(j >> 2, j & 3, w_score, sm.a);
        }
        GSYNC();
        // ---- B2: softmax + x_hat halves (128 jobs) ----
        for (int j = bid; j < 128; j += NBLK) {
            xhat_job(j >> 1, j & 1, b_yattn, sm.a);
        }
        GSYNC();
        // ---- D: zx (64, zp 4-5) + cfcx (48, fp 4-5) ----
        for (int j = bid; j < 112; j += NBLK) {
            if (j < 64) {
                int nt = j >> 1, ks = j & 1;
                gemm_mma(g_xhath + ks * 128, CIN,
                         g_w6h + (size_t)(nt * 64) * CAT + ks * 128, CAT, 128,
                         g_zp + (size_t)(4 + ks) * 64 * G4 + nt * 64, G4, nullptr, nullptr, sm.g);
            } else {
                int q = j - 64;
                int nt = q >> 1, ks = q & 1;
                gemm_mma(g_xhath + ks * 128, CIN,
                         g_w3h + (size_t)(nt * 64) * CAT + ks * 128, CAT, 128,
                         g_fp + (size_t)(4 + ks) * 64 * (3 * HH) + nt * 64, 3 * HH,
                         nullptr, nullptr, sm.g);
            }
        }
        GSYNC();
        // ---- E: LSTM pointwise (fold zp 0-5) ----
        for (int idx = bid * NTHR + tid; idx < BB * HH; idx += gstep) {
            int m = idx >> 9, u = idx & 511;
            float zi = b_ih[u], zg = b_ih[u + 512], zf = b_ih[u + 1024], zo = b_ih[u + 1536];
#pragma unroll
            for (int sl = 0; sl < 6; sl++) {
                const float* p = g_zp + (size_t)(sl * 64 + m) * G4;
                zi += p[u]; zg += p[u + 512]; zf += p[u + 1024]; zo += p[u + 1536];
            }
            float c_old = g_c[idx];
            float nc = c_old * sigm(zf + 1.0f) + tanhf(zi) * sigm(zg);
            g_c[idx] = nc;
            g_ch[idx] = __float2half_rn(nc);
            float hl = tanhf(nc) * sigm(zo);
            g_hlh[idx] = __float2half_rn(hl);
        }
        GSYNC();
        // ---- F: cfc h-part (96, fp 0-3) ----
        for (int j = bid; j < 96; j += NBLK) {
            int nt = j >> 2, ks = j & 3;
            gemm_mma(g_hlh + ks * 128, HH,
                     g_w3h + (size_t)(nt * 64) * CAT + CIN + ks * 128, CAT, 128,
                     g_fp + (size_t)ks * 64 * (3 * HH) + nt * 64, 3 * HH, nullptr, nullptr, sm.g);
        }
        GSYNC();
        // ---- G: CfC pointwise (fold fp 0-5) -> new h ----
        for (int idx = bid * NTHR + tid; idx < BB * HH; idx += gstep) {
            int m = idx >> 9, u = idx & 511;
            float f1 = g_b3[u], f2 = g_b3[u + 512], tg = g_b3[u + 1024];
#pragma unroll
            for (int sl = 0; sl < 6; sl++) {
                const float* p = g_fp + (size_t)(sl * 64 + m) * (3 * HH);
                f1 += p[u]; f2 += p[u + 512]; tg += p[u + 1024];
            }
            float ti = sigm(tg);
            float nh = tanhf(f1) * (1.0f - ti) + ti * tanhf(f2);
            g_h[idx] = nh;
            g_hh[idx] = __float2half_rn(nh);
        }
        GSYNC();
    }

    // ---- EP0: ctx from last-step scores (256 jobs) ----
    for (int j = bid; j < 256; j += NBLK) {
        ctx_job(j >> 2, j & 3, sm.a);
    }
    GSYNC();
    // ---- EP1: O1 GEMM ([h|ctx], K=1024): 64 jobs -> zp ----
    for (int j = bid; j < 64; j += NBLK) {
        int nt = j >> 3, ks = j & 7;
        const __half* A = (ks < 4) ? g_hh + ks * 128 : g_ctxh + (ks - 4) * 128;
        gemm_mma(A, HH, g_wo1h + (size_t)(nt * 64) * 1024 + ks * 128, 1024, 128,
                 g_zp + (size_t)ks * 64 * HH + nt * 64, HH, nullptr, nullptr, sm.g);
    }
    GSYNC();
    // ---- EP2: reduce 8 + leaky relu -> fp16 hid ----
    for (int idx = bid * NTHR + tid; idx < BB * HH; idx += gstep) {
        int m = idx >> 9, u = idx & 511;
        float s = b_o1[u];
#pragma unroll
        for (int sl = 0; sl < 8; sl++)
            s += g_zp[(size_t)(sl * 64 + m) * HH + u];
        g_hidh[idx] = __float2half_rn((s > 0.0f) ? s : 0.01f * s);
    }
    GSYNC();
    // ---- EP3: O2 GEMM (hid, K=512): 8 jobs -> fp ----
    for (int j = bid; j < 8; j += NBLK) {
        int nt = j >> 2, ks = j & 3;
        gemm_mma(g_hidh + ks * 128, HH,
                 g_wo2h + (size_t)(nt * 64) * HH + ks * 128, HH, 128,
                 g_fp + (size_t)ks * 64 * OUTN + nt * 64, OUTN, nullptr, nullptr, sm.g);
    }
    GSYNC();
    // ---- EP4: final reduce + bias (+ optional state copy) ----
    for (int idx = bid * NTHR + tid; idx < BB * OUTN; idx += gstep) {
        int m = idx >> 7, u = idx & 127;
        float s = b_o2[u];
#pragma unroll
        for (int sl = 0; sl < 4; sl++)
            s += g_fp[(size_t)(sl * 64 + m) * OUTN + u];
        out[idx] = s;
    }
    if (write_state) {
        for (int idx = bid * NTHR + tid; idx < BB * HH; idx += gstep) {
            out[BB * OUTN + idx] = g_h[idx];
            out[BB * OUTN + BB * HH + idx] = g_c[idx];
        }
    }
}

// ============================================================================
extern "C" void kernel_launch(void* const* d_in, const int* in_sizes, int n_in,
                              void* d_out, int out_size) {
    const float* x       = (const float*)d_in[0];
    const float* h_en    = (const float*)d_in[1];
    const float* W_dec   = (const float*)d_in[2];
    const float* W_enc   = (const float*)d_in[3];
    const float* b_enc   = (const float*)d_in[4];
    const float* w_score = (const float*)d_in[5];
    const float* W_yattn = (const float*)d_in[6];
    const float* b_yattn = (const float*)d_in[7];
    const float* W_ih    = (const float*)d_in[8];
    const float* b_ih    = (const float*)d_in[9];
    const float* W_hh    = (const float*)d_in[10];
    const float* W_ff1   = (const float*)d_in[11];
    const float* b_ff1   = (const float*)d_in[12];
    const float* W_ff2   = (const float*)d_in[13];
    const float* b_ff2   = (const float*)d_in[14];
    const float* W_ta    = (const float*)d_in[15];
    const float* b_ta    = (const float*)d_in[16];
    const float* W_tb    = (const float*)d_in[17];
    const float* b_tb    = (const float*)d_in[18];
    const float* W_o1    = (const float*)d_in[19];
    const float* b_o1    = (const float*)d_in[20];
    const float* W_o2    = (const float*)d_in[21];
    const float* b_o2    = (const float*)d_in[22];
    float* out = (float*)d_out;

    int write_state = (out_size >= BB * OUTN + 2 * BB * HH) ? 1 : 0;

    k_pack<<<512, 256>>>(x, h_en, W_dec, W_enc, W_yattn, W_ih, W_hh,
                         W_ff1, W_ff2, W_ta, W_tb,
                         b_ff1, b_ff2, b_ta, b_tb, W_o1, W_o2);
    k_main<<<NBLK, NTHR>>>(b_enc, w_score, b_yattn, b_ih,
                           b_o1, b_o2, out, write_state);
}